// round 13
// baseline (speedup 1.0000x reference)
#include <cuda_runtime.h>
#include <cuda_bf16.h>
#include <math.h>
#include <stdint.h>

// Problem constants
constexpr int S  = 2048;
constexpr int Bb = 2;
constexpr int E  = 1024;
constexpr int H  = 16;
constexpr int HD = 64;
constexpr int M  = S * Bb;   // 4096 rows

// ---------------------------------------------------------------------------
// Scratch (__device__ globals; allocation-free rule)
// ---------------------------------------------------------------------------
__device__ __align__(256) __nv_bfloat16 g_x_hi [M * E],     g_x_lo [M * E];
__device__ __align__(256) __nv_bfloat16 g_wt_hi[E * E],     g_wt_lo[E * E];
__device__ __align__(256) __nv_bfloat16 g_wi_hi[3 * E * E], g_wi_lo[3 * E * E];
__device__ __align__(256) __nv_bfloat16 g_wo_hi[E * E],     g_wo_lo[E * E];
__device__ __align__(256) __nv_bfloat16 g_xt_hi[M * E],     g_xt_lo[M * E];
__device__ __align__(256) __nv_bfloat16 g_qk_hi[(size_t)M * 3 * E];
__device__ __align__(256) __nv_bfloat16 g_qk_lo[(size_t)M * 3 * E];
__device__ __align__(256) __nv_bfloat16 g_oa_hi[M * E],     g_oa_lo[M * E];

// ---------------------------------------------------------------------------
// PTX helpers (baseline PTX only)
// ---------------------------------------------------------------------------
__device__ __forceinline__ uint32_t smem_u32(const void* p) {
    uint32_t a;
    asm("{ .reg .u64 t; cvta.to.shared.u64 t, %1; cvt.u32.u64 %0, t; }"
        : "=r"(a) : "l"(p));
    return a;
}

__device__ __forceinline__ void cp16(uint32_t dst, const void* src) {
    asm volatile("cp.async.cg.shared.global [%0], [%1], 16;"
                 :: "r"(dst), "l"(src) : "memory");
}
#define CP_COMMIT() asm volatile("cp.async.commit_group;" ::: "memory")
#define CP_WAIT(n)  asm volatile("cp.async.wait_group %0;" :: "n"(n) : "memory")

__device__ __forceinline__ void ldsm4(uint32_t* r, uint32_t addr) {
    asm volatile("ldmatrix.sync.aligned.m8n8.x4.shared.b16 {%0,%1,%2,%3}, [%4];"
                 : "=r"(r[0]), "=r"(r[1]), "=r"(r[2]), "=r"(r[3]) : "r"(addr));
}
__device__ __forceinline__ void ldsm4t(uint32_t* r, uint32_t addr) {
    asm volatile("ldmatrix.sync.aligned.m8n8.x4.trans.shared.b16 {%0,%1,%2,%3}, [%4];"
                 : "=r"(r[0]), "=r"(r[1]), "=r"(r[2]), "=r"(r[3]) : "r"(addr));
}

__device__ __forceinline__ void mma16816(float* d, const uint32_t* a,
                                         uint32_t b0, uint32_t b1) {
    asm volatile(
        "mma.sync.aligned.m16n8k16.row.col.f32.bf16.bf16.f32 "
        "{%0,%1,%2,%3}, {%4,%5,%6,%7}, {%8,%9}, {%0,%1,%2,%3};"
        : "+f"(d[0]), "+f"(d[1]), "+f"(d[2]), "+f"(d[3])
        : "r"(a[0]), "r"(a[1]), "r"(a[2]), "r"(a[3]), "r"(b0), "r"(b1));
}

// pack two fp32 -> bf16x2 (lo in lower half)
__device__ __forceinline__ uint32_t packbf(float lo, float hi) {
    uint32_t d;
    asm("cvt.rn.bf16x2.f32 %0, %1, %2;" : "=r"(d) : "f"(hi), "f"(lo));
    return d;
}

__device__ __forceinline__ float ex2f(float x) {
    float y;
    asm("ex2.approx.f32 %0, %1;" : "=f"(y) : "f"(x));
    return y;
}

// ---------------------------------------------------------------------------
// Fused fp32 -> (bf16 hi, bf16 lo) split over all four operands (R9 layout).
// ---------------------------------------------------------------------------
constexpr int SPL_N0 = 1048576;            // x
constexpr int SPL_N1 = SPL_N0 + 262144;    // + w_tor
constexpr int SPL_N2 = SPL_N1 + 786432;    // + in_w
constexpr int SPL_N3 = SPL_N2 + 262144;    // + out_w  (total)

__global__ void split_all(const float* __restrict__ x, const float* __restrict__ wt,
                          const float* __restrict__ wi, const float* __restrict__ wo,
                          __nv_bfloat16* __restrict__ xh, __nv_bfloat16* __restrict__ xl,
                          __nv_bfloat16* __restrict__ wth, __nv_bfloat16* __restrict__ wtl,
                          __nv_bfloat16* __restrict__ wih, __nv_bfloat16* __restrict__ wil,
                          __nv_bfloat16* __restrict__ woh, __nv_bfloat16* __restrict__ wol)
{
    int i = blockIdx.x * blockDim.x + threadIdx.x;
    if (i >= SPL_N3) return;
    const float* in; __nv_bfloat16 *hi, *lo; int base;
    if (i < SPL_N0)      { in = x;  hi = xh;  lo = xl;  base = 0; }
    else if (i < SPL_N1) { in = wt; hi = wth; lo = wtl; base = SPL_N0; }
    else if (i < SPL_N2) { in = wi; hi = wih; lo = wil; base = SPL_N1; }
    else                 { in = wo; hi = woh; lo = wol; base = SPL_N2; }
    i -= base;
    float4 v = ((const float4*)in)[i];
    __nv_bfloat16 h0 = __float2bfloat16(v.x);
    __nv_bfloat16 h1 = __float2bfloat16(v.y);
    __nv_bfloat16 h2 = __float2bfloat16(v.z);
    __nv_bfloat16 h3 = __float2bfloat16(v.w);
    __nv_bfloat16 l0 = __float2bfloat16(v.x - __bfloat162float(h0));
    __nv_bfloat16 l1 = __float2bfloat16(v.y - __bfloat162float(h1));
    __nv_bfloat16 l2 = __float2bfloat16(v.z - __bfloat162float(h2));
    __nv_bfloat16 l3 = __float2bfloat16(v.w - __bfloat162float(h3));
    ((__nv_bfloat162*)hi)[2 * i]     = __halves2bfloat162(h0, h1);
    ((__nv_bfloat162*)hi)[2 * i + 1] = __halves2bfloat162(h2, h3);
    ((__nv_bfloat162*)lo)[2 * i]     = __halves2bfloat162(l0, l1);
    ((__nv_bfloat162*)lo)[2 * i + 1] = __halves2bfloat162(l2, l3);
}

// ---------------------------------------------------------------------------
// HMMA bf16x3 GEMM: CTA tile 256x256, 512 threads / 16 warps (16 warps/SM,
// 1 CTA/SM), warp tile 64x64. BK=32, double buffer, single-sync pipeline.
// L2 fill traffic per output element is 2x lower than the 128x128 tile.
// ---------------------------------------------------------------------------
constexpr int RBg     = 80;                 // padded row bytes (64B data + 16 pad)
constexpr int TILEg   = 256 * RBg;          // 20480 per operand tile
constexpr int STAGEg  = 4 * TILEg;          // 81920 (Ah, Al, Bh, Bl)
constexpr int GSMEM   = 2 * STAGEg;         // 163840 -> 1 CTA/SM

template<int MODE>
__global__ __launch_bounds__(512, 1) void gemm_bf16x3_hmma(
    const __nv_bfloat16* __restrict__ Ahp, const __nv_bfloat16* __restrict__ Alp,
    const __nv_bfloat16* __restrict__ Bhp, const __nv_bfloat16* __restrict__ Blp,
    const float* __restrict__ bias,
    float* __restrict__ Cf,
    __nv_bfloat16* __restrict__ Chi, __nv_bfloat16* __restrict__ Clo,
    int Nn, int Kk)
{
    extern __shared__ char smem[];
    const uint32_t sb = smem_u32(smem);

    const int tid  = threadIdx.x;             // 0..511
    const int wid  = tid >> 5;                 // 0..15
    const int lane = tid & 31;
    const int m0 = blockIdx.y * 256;
    const int n0 = blockIdx.x * 256;

    const __nv_bfloat16* bases[4] = { Ahp, Alp, Bhp, Blp };

    auto load_stage = [&](int st, int k0) {
        #pragma unroll
        for (int p = 0; p < 2; p++) {
            int idx = tid + p * 512;           // 0..1023
            int t   = idx >> 8;                // tile 0..3
            int row = idx & 255;
            int gr  = (t < 2 ? m0 : n0) + row;
            const __nv_bfloat16* s = bases[t] + (size_t)gr * Kk + k0;
            uint32_t d = sb + st * STAGEg + t * TILEg + row * RBg;
            cp16(d,      s);
            cp16(d + 16, s + 8);
            cp16(d + 32, s + 16);
            cp16(d + 48, s + 24);
        }
    };

    float acc[4][8][4];
    #pragma unroll
    for (int i = 0; i < 4; i++)
        #pragma unroll
        for (int j = 0; j < 8; j++)
            #pragma unroll
            for (int q = 0; q < 4; q++) acc[i][j][q] = 0.f;

    const int wm = (wid & 3) * 64;     // 4 m-groups
    const int wn = (wid >> 2) * 64;    // 4 n-groups
    const int lr  = lane & 15;
    const int lcb = (lane >> 4) * 16;

    const int NCH = Kk / 32;
    load_stage(0, 0);
    CP_COMMIT();

    for (int c = 0; c < NCH; c++) {
        CP_WAIT(0);
        __syncthreads();
        if (c + 1 < NCH) { load_stage((c + 1) & 1, (c + 1) * 32); CP_COMMIT(); }

        const uint32_t stb = sb + (c & 1) * STAGEg;
        #pragma unroll
        for (int ks = 0; ks < 2; ks++) {
            const uint32_t koff = ks * 32 + lcb;
            uint32_t ah[4][4], al[4][4], bf[4][4];

            uint32_t aad = stb + (wm + lr) * RBg + koff;
            #pragma unroll
            for (int f = 0; f < 4; f++) ldsm4(ah[f], aad + f * 16 * RBg);

            uint32_t bad = stb + 2 * TILEg + (wn + lr) * RBg + koff;
            #pragma unroll
            for (int f = 0; f < 4; f++) ldsm4(bf[f], bad + f * 16 * RBg);

            // pass 1: Ah * Bh
            #pragma unroll
            for (int mi = 0; mi < 4; mi++)
                #pragma unroll
                for (int nj = 0; nj < 8; nj++)
                    mma16816(acc[mi][nj], ah[mi], bf[nj >> 1][nj & 1], bf[nj >> 1][2 + (nj & 1)]);

            // pass 2: Al * Bh
            uint32_t aal = stb + TILEg + (wm + lr) * RBg + koff;
            #pragma unroll
            for (int f = 0; f < 4; f++) ldsm4(al[f], aal + f * 16 * RBg);
            #pragma unroll
            for (int mi = 0; mi < 4; mi++)
                #pragma unroll
                for (int nj = 0; nj < 8; nj++)
                    mma16816(acc[mi][nj], al[mi], bf[nj >> 1][nj & 1], bf[nj >> 1][2 + (nj & 1)]);

            // pass 3: Ah * Bl (overwrite B fragments)
            uint32_t bbl = stb + 3 * TILEg + (wn + lr) * RBg + koff;
            #pragma unroll
            for (int f = 0; f < 4; f++) ldsm4(bf[f], bbl + f * 16 * RBg);
            #pragma unroll
            for (int mi = 0; mi < 4; mi++)
                #pragma unroll
                for (int nj = 0; nj < 8; nj++)
                    mma16816(acc[mi][nj], ah[mi], bf[nj >> 1][nj & 1], bf[nj >> 1][2 + (nj & 1)]);
        }
    }

    const int rbase = m0 + wm + (lane >> 2);
    const int cbase = n0 + wn + (lane & 3) * 2;
    #pragma unroll
    for (int mi = 0; mi < 4; mi++) {
        #pragma unroll
        for (int nj = 0; nj < 8; nj++) {
            const int cc = cbase + nj * 8;
            float2 bv = *(const float2*)&bias[cc];
            const int r0 = rbase + mi * 16;
            float v0 = acc[mi][nj][0] + bv.x;
            float v1 = acc[mi][nj][1] + bv.y;
            float v2 = acc[mi][nj][2] + bv.x;
            float v3 = acc[mi][nj][3] + bv.y;
            if (MODE == 0) {
                *(float2*)&Cf[(size_t)r0 * Nn + cc]       = make_float2(v0, v1);
                *(float2*)&Cf[(size_t)(r0 + 8) * Nn + cc] = make_float2(v2, v3);
            } else {
                __nv_bfloat16 h0 = __float2bfloat16(v0), h1 = __float2bfloat16(v1);
                __nv_bfloat16 h2 = __float2bfloat16(v2), h3 = __float2bfloat16(v3);
                __nv_bfloat16 l0 = __float2bfloat16(v0 - __bfloat162float(h0));
                __nv_bfloat16 l1 = __float2bfloat16(v1 - __bfloat162float(h1));
                __nv_bfloat16 l2 = __float2bfloat16(v2 - __bfloat162float(h2));
                __nv_bfloat16 l3 = __float2bfloat16(v3 - __bfloat162float(h3));
                *(__nv_bfloat162*)&Chi[(size_t)r0 * Nn + cc]       = __halves2bfloat162(h0, h1);
                *(__nv_bfloat162*)&Chi[(size_t)(r0 + 8) * Nn + cc] = __halves2bfloat162(h2, h3);
                *(__nv_bfloat162*)&Clo[(size_t)r0 * Nn + cc]       = __halves2bfloat162(l0, l1);
                *(__nv_bfloat162*)&Clo[(size_t)(r0 + 8) * Nn + cc] = __halves2bfloat162(l2, l3);
            }
        }
    }
}

// ---------------------------------------------------------------------------
// HMMA flash-attention (unchanged from R9: 2-pass QK, 3-pass PV, fixed-max)
// ---------------------------------------------------------------------------
constexpr int ARD    = 144;
constexpr int AQTILE = 128 * ARD;
constexpr int AQH = 0, AQL = AQTILE;
constexpr int ASTG0  = 2 * AQTILE;
constexpr int KTILE  = 64 * ARD;
constexpr int ASTGB  = 3 * KTILE;
constexpr int AKH = 0, AVH = KTILE, AVL = 2 * KTILE;
constexpr int ASMEM  = ASTG0 + 2 * ASTGB;

__global__ __launch_bounds__(256, 2) void attn_toroidal_mma(
    const __nv_bfloat16* __restrict__ qkh, const __nv_bfloat16* __restrict__ qkl,
    __nv_bfloat16* __restrict__ ohi, __nv_bfloat16* __restrict__ olo)
{
    extern __shared__ char smc[];
    const uint32_t sb = smem_u32(smc);
    const int tid = threadIdx.x, wid = tid >> 5, lane = tid & 31;
    const int bh = blockIdx.x, b = bh >> 4, h = bh & 15;
    const int q0 = blockIdx.y * 128;

    const size_t RS = 6144;
    const __nv_bfloat16* qh_p = qkh + (size_t)b * 3 * E + h * HD;
    const __nv_bfloat16* ql_p = qkl + (size_t)b * 3 * E + h * HD;
    const __nv_bfloat16* kh_p = qh_p + E;
    const __nv_bfloat16* vh_p = qh_p + 2 * E;
    const __nv_bfloat16* vl_p = ql_p + 2 * E;

    auto load_q = [&]() {
        #pragma unroll
        for (int i = 0; i < 4; i++) {
            int cid = tid + i * 256;
            int row = cid >> 3, ch = cid & 7;
            uint32_t d = sb + row * ARD + ch * 16;
            cp16(d + AQH, qh_p + (size_t)(q0 + row) * RS + ch * 8);
            cp16(d + AQL, ql_p + (size_t)(q0 + row) * RS + ch * 8);
        }
    };
    auto load_kv = [&](int st, int kt) {
        const __nv_bfloat16* bases[3] = { kh_p, vh_p, vl_p };
        uint32_t stg = sb + ASTG0 + st * ASTGB;
        #pragma unroll
        for (int t = 0; t < 3; t++) {
            #pragma unroll
            for (int i = 0; i < 2; i++) {
                int cid = tid + i * 256;
                int row = cid >> 3, ch = cid & 7;
                cp16(stg + t * KTILE + row * ARD + ch * 16,
                     bases[t] + (size_t)(kt * 64 + row) * RS + ch * 8);
            }
        }
    };

    load_q();
    load_kv(0, 0);
    CP_COMMIT();

    const int lr4 = lane >> 2;
    const int lc2 = (lane & 3) * 2;
    const int rowA = q0 + wid * 16 + lr4;
    const int rowB = rowA + 8;

    float Ov[8][4];
    #pragma unroll
    for (int j = 0; j < 8; j++)
        #pragma unroll
        for (int q = 0; q < 4; q++) Ov[j][q] = 0.f;
    float lA = 0.f, lB = 0.f;

    const uint32_t lrow = lane & 15;
    const uint32_t lcb  = (lane >> 4) * 16;
    const uint32_t qaddr0 = sb + (wid * 16 + lrow) * ARD + lcb;

    CP_WAIT(0);
    __syncthreads();
    uint32_t qh_f[4][4];
    #pragma unroll
    for (int ks = 0; ks < 4; ks++) ldsm4(qh_f[ks], qaddr0 + AQH + ks * 32);
    constexpr int NT = S / 64;
    load_kv(1, 1);
    CP_COMMIT();

    const float C1 = 0.18033688f;
    const float CB = 1.44269504f;

    for (int kt = 0; kt < NT; kt++) {
        if (kt > 0) {
            CP_WAIT(0);
            __syncthreads();
            if (kt + 1 < NT) { load_kv((kt + 1) & 1, kt + 1); CP_COMMIT(); }
        }
        const uint32_t stg = sb + ASTG0 + (kt & 1) * ASTGB;

        float Sv[8][4];
        #pragma unroll
        for (int nj = 0; nj < 8; nj++)
            #pragma unroll
            for (int q = 0; q < 4; q++) Sv[nj][q] = 0.f;

        #pragma unroll
        for (int ks = 0; ks < 4; ks++) {
            uint32_t al[4], kf[4][4];
            ldsm4(al, qaddr0 + AQL + ks * 32);
            uint32_t kaddr = stg + AKH + lrow * ARD + ks * 32 + lcb;
            #pragma unroll
            for (int kb = 0; kb < 4; kb++) ldsm4(kf[kb], kaddr + kb * 16 * ARD);
            #pragma unroll
            for (int nj = 0; nj < 8; nj++) {
                uint32_t b0 = kf[nj >> 1][nj & 1], b1 = kf[nj >> 1][2 + (nj & 1)];
                mma16816(Sv[nj], qh_f[ks], b0, b1);
                mma16816(Sv[nj], al, b0, b1);
            }
        }

        const int wband = (kt * 64 - (q0 + wid * 16)) & (S - 1);
        if (wband <= 16 || wband >= S - 64) {
            const int baseA = kt * 64 + lc2 - rowA + 1;
            const int baseB = baseA - 8;
            #pragma unroll
            for (int nj = 0; nj < 8; nj++) {
                int u0 = (baseA + nj * 8)     & (S - 1);
                int u1 = (baseA + nj * 8 + 1) & (S - 1);
                int u2 = (baseB + nj * 8)     & (S - 1);
                int u3 = (baseB + nj * 8 + 1) & (S - 1);
                Sv[nj][0] = ex2f(Sv[nj][0] * C1 + (u0 <= 2 ? CB : 0.f));
                Sv[nj][1] = ex2f(Sv[nj][1] * C1 + (u1 <= 2 ? CB : 0.f));
                Sv[nj][2] = ex2f(Sv[nj][2] * C1 + (u2 <= 2 ? CB : 0.f));
                Sv[nj][3] = ex2f(Sv[nj][3] * C1 + (u3 <= 2 ? CB : 0.f));
                lA += Sv[nj][0] + Sv[nj][1];
                lB += Sv[nj][2] + Sv[nj][3];
            }
        } else {
            #pragma unroll
            for (int nj = 0; nj < 8; nj++) {
                Sv[nj][0] = ex2f(Sv[nj][0] * C1);
                Sv[nj][1] = ex2f(Sv[nj][1] * C1);
                Sv[nj][2] = ex2f(Sv[nj][2] * C1);
                Sv[nj][3] = ex2f(Sv[nj][3] * C1);
                lA += Sv[nj][0] + Sv[nj][1];
                lB += Sv[nj][2] + Sv[nj][3];
            }
        }

        #pragma unroll
        for (int kb = 0; kb < 4; kb++) {
            uint32_t ph[4], pl[4];
            #pragma unroll
            for (int half = 0; half < 2; half++) {
                const float* c = Sv[2 * kb + half];
                uint32_t p01 = packbf(c[0], c[1]);
                uint32_t p23 = packbf(c[2], c[3]);
                ph[half * 2]     = p01;
                ph[half * 2 + 1] = p23;
                float r0 = c[0] - __uint_as_float(p01 << 16);
                float r1 = c[1] - __uint_as_float(p01 & 0xffff0000u);
                float r2 = c[2] - __uint_as_float(p23 << 16);
                float r3 = c[3] - __uint_as_float(p23 & 0xffff0000u);
                pl[half * 2]     = packbf(r0, r1);
                pl[half * 2 + 1] = packbf(r2, r3);
            }
            uint32_t vaddr = stg + AVH + (kb * 16 + lrow) * ARD + lcb;
            #pragma unroll
            for (int db = 0; db < 4; db++) {
                uint32_t vh4[4], vl4[4];
                ldsm4t(vh4, vaddr + db * 32);
                mma16816(Ov[2 * db],     ph, vh4[0], vh4[1]);
                mma16816(Ov[2 * db + 1], ph, vh4[2], vh4[3]);
                mma16816(Ov[2 * db],     pl, vh4[0], vh4[1]);
                mma16816(Ov[2 * db + 1], pl, vh4[2], vh4[3]);
                ldsm4t(vl4, vaddr + KTILE + db * 32);
                mma16816(Ov[2 * db],     ph, vl4[0], vl4[1]);
                mma16816(Ov[2 * db + 1], ph, vl4[2], vl4[3]);
            }
        }
    }

    lA += __shfl_xor_sync(0xffffffffu, lA, 1);
    lA += __shfl_xor_sync(0xffffffffu, lA, 2);
    lB += __shfl_xor_sync(0xffffffffu, lB, 1);
    lB += __shfl_xor_sync(0xffffffffu, lB, 2);
    const float invA = 1.f / lA, invB = 1.f / lB;
    const size_t oA = ((size_t)rowA * Bb + b) * E + h * HD;
    const size_t oB = ((size_t)rowB * Bb + b) * E + h * HD;
    #pragma unroll
    for (int nj = 0; nj < 8; nj++) {
        const int dc = nj * 8 + lc2;
        float v0 = Ov[nj][0] * invA, v1 = Ov[nj][1] * invA;
        float v2 = Ov[nj][2] * invB, v3 = Ov[nj][3] * invB;
        uint32_t hA = packbf(v0, v1);
        uint32_t hB = packbf(v2, v3);
        float r0 = v0 - __uint_as_float(hA << 16);
        float r1 = v1 - __uint_as_float(hA & 0xffff0000u);
        float r2 = v2 - __uint_as_float(hB << 16);
        float r3 = v3 - __uint_as_float(hB & 0xffff0000u);
        *(uint32_t*)&ohi[oA + dc] = hA;
        *(uint32_t*)&ohi[oB + dc] = hB;
        *(uint32_t*)&olo[oA + dc] = packbf(r0, r1);
        *(uint32_t*)&olo[oB + dc] = packbf(r2, r3);
    }
}

// ---------------------------------------------------------------------------
// Host side
// ---------------------------------------------------------------------------
extern "C" void kernel_launch(void* const* d_in, const int* in_sizes, int n_in,
                              void* d_out, int out_size)
{
    (void)in_sizes; (void)n_in; (void)out_size;
    const float* x     = (const float*)d_in[0];
    const float* w_tor = (const float*)d_in[1];
    const float* b_tor = (const float*)d_in[2];
    const float* in_w  = (const float*)d_in[3];
    const float* in_b  = (const float*)d_in[4];
    const float* out_w = (const float*)d_in[5];
    const float* out_b = (const float*)d_in[6];
    float* out = (float*)d_out;

    __nv_bfloat16 *x_hi, *x_lo, *wt_hi, *wt_lo, *wi_hi, *wi_lo, *wo_hi, *wo_lo;
    __nv_bfloat16 *xt_hi, *xt_lo, *qk_hi, *qk_lo, *oa_hi, *oa_lo;
    cudaGetSymbolAddress((void**)&x_hi,  g_x_hi);  cudaGetSymbolAddress((void**)&x_lo,  g_x_lo);
    cudaGetSymbolAddress((void**)&wt_hi, g_wt_hi); cudaGetSymbolAddress((void**)&wt_lo, g_wt_lo);
    cudaGetSymbolAddress((void**)&wi_hi, g_wi_hi); cudaGetSymbolAddress((void**)&wi_lo, g_wi_lo);
    cudaGetSymbolAddress((void**)&wo_hi, g_wo_hi); cudaGetSymbolAddress((void**)&wo_lo, g_wo_lo);
    cudaGetSymbolAddress((void**)&xt_hi, g_xt_hi); cudaGetSymbolAddress((void**)&xt_lo, g_xt_lo);
    cudaGetSymbolAddress((void**)&qk_hi, g_qk_hi); cudaGetSymbolAddress((void**)&qk_lo, g_qk_lo);
    cudaGetSymbolAddress((void**)&oa_hi, g_oa_hi); cudaGetSymbolAddress((void**)&oa_lo, g_oa_lo);

    cudaFuncSetAttribute(gemm_bf16x3_hmma<0>, cudaFuncAttributeMaxDynamicSharedMemorySize, GSMEM);
    cudaFuncSetAttribute(gemm_bf16x3_hmma<1>, cudaFuncAttributeMaxDynamicSharedMemorySize, GSMEM);
    cudaFuncSetAttribute(attn_toroidal_mma, cudaFuncAttributeMaxDynamicSharedMemorySize, ASMEM);

    split_all<<<(SPL_N3 + 255) / 256, 256>>>(x, w_tor, in_w, out_w,
        x_hi, x_lo, wt_hi, wt_lo, wi_hi, wi_lo, wo_hi, wo_lo);

    // 1. xt = x @ w_tor^T + b_tor  (split bf16 output)   grid (4, 16)
    gemm_bf16x3_hmma<1><<<dim3(E / 256, M / 256), 512, GSMEM>>>(
        x_hi, x_lo, wt_hi, wt_lo, b_tor, nullptr, xt_hi, xt_lo, E, E);
    // 2. qkv = xt @ in_proj_w^T + in_proj_b  (split bf16 output)  grid (12, 16)
    gemm_bf16x3_hmma<1><<<dim3(3 * E / 256, M / 256), 512, GSMEM>>>(
        xt_hi, xt_lo, wi_hi, wi_lo, in_b, nullptr, qk_hi, qk_lo, 3 * E, E);
    // 3. attention (HMMA, 2-pass QK / 3-pass PV, split bf16 output)
    attn_toroidal_mma<<<dim3(Bb * H, S / 128), 256, ASMEM>>>(qk_hi, qk_lo, oa_hi, oa_lo);
    // 4. out = o @ out_w^T + out_b  (fp32 output)   grid (4, 16)
    gemm_bf16x3_hmma<0><<<dim3(E / 256, M / 256), 512, GSMEM>>>(
        oa_hi, oa_lo, wo_hi, wo_lo, out_b, out, nullptr, nullptr, E, E);
}

// round 14
// speedup vs baseline: 2.8482x; 2.8482x over previous
#include <cuda_runtime.h>
#include <cuda_bf16.h>
#include <math.h>
#include <stdint.h>

// Problem constants
constexpr int S  = 2048;
constexpr int Bb = 2;
constexpr int E  = 1024;
constexpr int H  = 16;
constexpr int HD = 64;
constexpr int M  = S * Bb;   // 4096 rows

// ---------------------------------------------------------------------------
// Scratch (__device__ globals; allocation-free rule)
// ---------------------------------------------------------------------------
__device__ __align__(256) __nv_bfloat16 g_x_hi [M * E],     g_x_lo [M * E];
__device__ __align__(256) __nv_bfloat16 g_wt_hi[E * E],     g_wt_lo[E * E];
__device__ __align__(256) __nv_bfloat16 g_wi_hi[3 * E * E], g_wi_lo[3 * E * E];
__device__ __align__(256) __nv_bfloat16 g_wo_hi[E * E],     g_wo_lo[E * E];
__device__ __align__(256) __nv_bfloat16 g_xt_hi[M * E],     g_xt_lo[M * E];
__device__ __align__(256) __nv_bfloat16 g_qk_hi[(size_t)M * 3 * E];
__device__ __align__(256) __nv_bfloat16 g_qk_lo[(size_t)M * 3 * E];
__device__ __align__(256) __nv_bfloat16 g_oa_hi[M * E],     g_oa_lo[M * E];

// ---------------------------------------------------------------------------
// PTX helpers (baseline PTX only)
// ---------------------------------------------------------------------------
__device__ __forceinline__ uint32_t smem_u32(const void* p) {
    uint32_t a;
    asm("{ .reg .u64 t; cvta.to.shared.u64 t, %1; cvt.u32.u64 %0, t; }"
        : "=r"(a) : "l"(p));
    return a;
}

__device__ __forceinline__ void cp16(uint32_t dst, const void* src) {
    asm volatile("cp.async.cg.shared.global [%0], [%1], 16;"
                 :: "r"(dst), "l"(src) : "memory");
}
#define CP_COMMIT() asm volatile("cp.async.commit_group;" ::: "memory")
#define CP_WAIT(n)  asm volatile("cp.async.wait_group %0;" :: "n"(n) : "memory")

__device__ __forceinline__ void ldsm4(uint32_t* r, uint32_t addr) {
    asm volatile("ldmatrix.sync.aligned.m8n8.x4.shared.b16 {%0,%1,%2,%3}, [%4];"
                 : "=r"(r[0]), "=r"(r[1]), "=r"(r[2]), "=r"(r[3]) : "r"(addr));
}
__device__ __forceinline__ void ldsm4t(uint32_t* r, uint32_t addr) {
    asm volatile("ldmatrix.sync.aligned.m8n8.x4.trans.shared.b16 {%0,%1,%2,%3}, [%4];"
                 : "=r"(r[0]), "=r"(r[1]), "=r"(r[2]), "=r"(r[3]) : "r"(addr));
}

__device__ __forceinline__ void mma16816(float* d, const uint32_t* a,
                                         uint32_t b0, uint32_t b1) {
    asm volatile(
        "mma.sync.aligned.m16n8k16.row.col.f32.bf16.bf16.f32 "
        "{%0,%1,%2,%3}, {%4,%5,%6,%7}, {%8,%9}, {%0,%1,%2,%3};"
        : "+f"(d[0]), "+f"(d[1]), "+f"(d[2]), "+f"(d[3])
        : "r"(a[0]), "r"(a[1]), "r"(a[2]), "r"(a[3]), "r"(b0), "r"(b1));
}

// pack two fp32 -> bf16x2 (lo in lower half)
__device__ __forceinline__ uint32_t packbf(float lo, float hi) {
    uint32_t d;
    asm("cvt.rn.bf16x2.f32 %0, %1, %2;" : "=r"(d) : "f"(hi), "f"(lo));
    return d;
}

__device__ __forceinline__ float ex2f(float x) {
    float y;
    asm("ex2.approx.f32 %0, %1;" : "=f"(y) : "f"(x));
    return y;
}

// ---------------------------------------------------------------------------
// Fused fp32 -> (bf16 hi, bf16 lo) split over all four operands (R9 layout).
// ---------------------------------------------------------------------------
constexpr int SPL_N0 = 1048576;            // x
constexpr int SPL_N1 = SPL_N0 + 262144;    // + w_tor
constexpr int SPL_N2 = SPL_N1 + 786432;    // + in_w
constexpr int SPL_N3 = SPL_N2 + 262144;    // + out_w  (total)

__global__ void split_all(const float* __restrict__ x, const float* __restrict__ wt,
                          const float* __restrict__ wi, const float* __restrict__ wo,
                          __nv_bfloat16* __restrict__ xh, __nv_bfloat16* __restrict__ xl,
                          __nv_bfloat16* __restrict__ wth, __nv_bfloat16* __restrict__ wtl,
                          __nv_bfloat16* __restrict__ wih, __nv_bfloat16* __restrict__ wil,
                          __nv_bfloat16* __restrict__ woh, __nv_bfloat16* __restrict__ wol)
{
    int i = blockIdx.x * blockDim.x + threadIdx.x;
    if (i >= SPL_N3) return;
    const float* in; __nv_bfloat16 *hi, *lo; int base;
    if (i < SPL_N0)      { in = x;  hi = xh;  lo = xl;  base = 0; }
    else if (i < SPL_N1) { in = wt; hi = wth; lo = wtl; base = SPL_N0; }
    else if (i < SPL_N2) { in = wi; hi = wih; lo = wil; base = SPL_N1; }
    else                 { in = wo; hi = woh; lo = wol; base = SPL_N2; }
    i -= base;
    float4 v = ((const float4*)in)[i];
    __nv_bfloat16 h0 = __float2bfloat16(v.x);
    __nv_bfloat16 h1 = __float2bfloat16(v.y);
    __nv_bfloat16 h2 = __float2bfloat16(v.z);
    __nv_bfloat16 h3 = __float2bfloat16(v.w);
    __nv_bfloat16 l0 = __float2bfloat16(v.x - __bfloat162float(h0));
    __nv_bfloat16 l1 = __float2bfloat16(v.y - __bfloat162float(h1));
    __nv_bfloat16 l2 = __float2bfloat16(v.z - __bfloat162float(h2));
    __nv_bfloat16 l3 = __float2bfloat16(v.w - __bfloat162float(h3));
    ((__nv_bfloat162*)hi)[2 * i]     = __halves2bfloat162(h0, h1);
    ((__nv_bfloat162*)hi)[2 * i + 1] = __halves2bfloat162(h2, h3);
    ((__nv_bfloat162*)lo)[2 * i]     = __halves2bfloat162(l0, l1);
    ((__nv_bfloat162*)lo)[2 * i + 1] = __halves2bfloat162(l2, l3);
}

// ---------------------------------------------------------------------------
// HMMA bf16x3 GEMM — proven R9 config: CTA 128x128, 8 warps (warp 32x64),
// BK=32, double buffer, single-sync pipeline, 80B padded rows, 2 CTAs/SM.
// MODE 0: fp32 C.  MODE 1: split (hi, lo) bf16 C.
// MODE 2: like MODE 1 but skip lo stores for columns in [E, 2E) (the K third
//         of qkv — attention's 2-pass QK never reads k_lo).
// ---------------------------------------------------------------------------
constexpr int RB      = 80;
constexpr int TILE_B  = 128 * RB;
constexpr int STAGE_B = 4 * TILE_B;
constexpr int GSMEM   = 2 * STAGE_B;

template<int MODE>
__global__ __launch_bounds__(256, 2) void gemm_bf16x3_hmma(
    const __nv_bfloat16* __restrict__ Ahp, const __nv_bfloat16* __restrict__ Alp,
    const __nv_bfloat16* __restrict__ Bhp, const __nv_bfloat16* __restrict__ Blp,
    const float* __restrict__ bias,
    float* __restrict__ Cf,
    __nv_bfloat16* __restrict__ Chi, __nv_bfloat16* __restrict__ Clo,
    int Nn, int Kk)
{
    extern __shared__ char smem[];
    const uint32_t sb = smem_u32(smem);

    const int tid  = threadIdx.x;
    const int wid  = tid >> 5;
    const int lane = tid & 31;
    const int m0 = blockIdx.y * 128;
    const int n0 = blockIdx.x * 128;

    const int lrow = tid >> 1;
    const int lhalf = (tid & 1) * 32;
    const __nv_bfloat16* srcs[4] = {
        Ahp + (size_t)(m0 + lrow) * Kk,
        Alp + (size_t)(m0 + lrow) * Kk,
        Bhp + (size_t)(n0 + lrow) * Kk,
        Blp + (size_t)(n0 + lrow) * Kk };

    auto load_stage = [&](int st, int k0) {
        uint32_t dbase = sb + st * STAGE_B + lrow * RB + lhalf;
        #pragma unroll
        for (int t = 0; t < 4; t++) {
            const __nv_bfloat16* s = srcs[t] + k0 + (lhalf >> 1);
            cp16(dbase + t * TILE_B,      s);
            cp16(dbase + t * TILE_B + 16, s + 8);
        }
    };

    float acc[2][8][4];
    #pragma unroll
    for (int i = 0; i < 2; i++)
        #pragma unroll
        for (int j = 0; j < 8; j++)
            #pragma unroll
            for (int q = 0; q < 4; q++) acc[i][j][q] = 0.f;

    const int wm = (wid & 3) * 32;
    const int wn = (wid >> 2) * 64;
    const int lr  = lane & 15;
    const int lc  = (lane >> 4) * 16;

    const int NCH = Kk / 32;
    load_stage(0, 0);
    CP_COMMIT();

    for (int c = 0; c < NCH; c++) {
        CP_WAIT(0);
        __syncthreads();
        if (c + 1 < NCH) { load_stage((c + 1) & 1, (c + 1) * 32); CP_COMMIT(); }

        const uint32_t stb = sb + (c & 1) * STAGE_B;
        #pragma unroll
        for (int ks = 0; ks < 2; ks++) {
            const uint32_t koff = ks * 32 + lc;
            uint32_t ah[2][4], al[2][4], bb[4][4];

            uint32_t aad = stb + (wm + lr) * RB + koff;
            ldsm4(ah[0], aad);
            ldsm4(ah[1], aad + 16 * RB);

            uint32_t bad = stb + 2 * TILE_B + (wn + lr) * RB + koff;
            ldsm4(bb[0], bad);
            ldsm4(bb[1], bad + 16 * RB);
            ldsm4(bb[2], bad + 32 * RB);
            ldsm4(bb[3], bad + 48 * RB);

            #pragma unroll
            for (int mi = 0; mi < 2; mi++)
                #pragma unroll
                for (int nj = 0; nj < 8; nj++)
                    mma16816(acc[mi][nj], ah[mi], bb[nj >> 1][nj & 1], bb[nj >> 1][2 + (nj & 1)]);

            uint32_t aal = stb + TILE_B + (wm + lr) * RB + koff;
            ldsm4(al[0], aal);
            ldsm4(al[1], aal + 16 * RB);
            #pragma unroll
            for (int mi = 0; mi < 2; mi++)
                #pragma unroll
                for (int nj = 0; nj < 8; nj++)
                    mma16816(acc[mi][nj], al[mi], bb[nj >> 1][nj & 1], bb[nj >> 1][2 + (nj & 1)]);

            uint32_t bbl = stb + 3 * TILE_B + (wn + lr) * RB + koff;
            ldsm4(bb[0], bbl);
            ldsm4(bb[1], bbl + 16 * RB);
            ldsm4(bb[2], bbl + 32 * RB);
            ldsm4(bb[3], bbl + 48 * RB);
            #pragma unroll
            for (int mi = 0; mi < 2; mi++)
                #pragma unroll
                for (int nj = 0; nj < 8; nj++)
                    mma16816(acc[mi][nj], ah[mi], bb[nj >> 1][nj & 1], bb[nj >> 1][2 + (nj & 1)]);
        }
    }

    const int rbase = m0 + wm + (lane >> 2);
    const int cbase = n0 + wn + (lane & 3) * 2;
    #pragma unroll
    for (int mi = 0; mi < 2; mi++) {
        #pragma unroll
        for (int nj = 0; nj < 8; nj++) {
            const int cc = cbase + nj * 8;
            float2 bv = *(const float2*)&bias[cc];
            const int r0 = rbase + mi * 16;
            float v0 = acc[mi][nj][0] + bv.x;
            float v1 = acc[mi][nj][1] + bv.y;
            float v2 = acc[mi][nj][2] + bv.x;
            float v3 = acc[mi][nj][3] + bv.y;
            if (MODE == 0) {
                *(float2*)&Cf[(size_t)r0 * Nn + cc]       = make_float2(v0, v1);
                *(float2*)&Cf[(size_t)(r0 + 8) * Nn + cc] = make_float2(v2, v3);
            } else {
                __nv_bfloat16 h0 = __float2bfloat16(v0), h1 = __float2bfloat16(v1);
                __nv_bfloat16 h2 = __float2bfloat16(v2), h3 = __float2bfloat16(v3);
                *(__nv_bfloat162*)&Chi[(size_t)r0 * Nn + cc]       = __halves2bfloat162(h0, h1);
                *(__nv_bfloat162*)&Chi[(size_t)(r0 + 8) * Nn + cc] = __halves2bfloat162(h2, h3);
                // k_lo is never read by the 2-pass-QK attention: skip in MODE 2.
                if (MODE == 1 || cc < E || cc >= 2 * E) {
                    __nv_bfloat16 l0 = __float2bfloat16(v0 - __bfloat162float(h0));
                    __nv_bfloat16 l1 = __float2bfloat16(v1 - __bfloat162float(h1));
                    __nv_bfloat16 l2 = __float2bfloat16(v2 - __bfloat162float(h2));
                    __nv_bfloat16 l3 = __float2bfloat16(v3 - __bfloat162float(h3));
                    *(__nv_bfloat162*)&Clo[(size_t)r0 * Nn + cc]       = __halves2bfloat162(l0, l1);
                    *(__nv_bfloat162*)&Clo[(size_t)(r0 + 8) * Nn + cc] = __halves2bfloat162(l2, l3);
                }
            }
        }
    }
}

// ---------------------------------------------------------------------------
// HMMA flash-attention (unchanged from R9: 2-pass QK, 3-pass PV, fixed-max)
// ---------------------------------------------------------------------------
constexpr int ARD    = 144;
constexpr int AQTILE = 128 * ARD;
constexpr int AQH = 0, AQL = AQTILE;
constexpr int ASTG0  = 2 * AQTILE;
constexpr int KTILE  = 64 * ARD;
constexpr int ASTGB  = 3 * KTILE;
constexpr int AKH = 0, AVH = KTILE, AVL = 2 * KTILE;
constexpr int ASMEM  = ASTG0 + 2 * ASTGB;

__global__ __launch_bounds__(256, 2) void attn_toroidal_mma(
    const __nv_bfloat16* __restrict__ qkh, const __nv_bfloat16* __restrict__ qkl,
    __nv_bfloat16* __restrict__ ohi, __nv_bfloat16* __restrict__ olo)
{
    extern __shared__ char smc[];
    const uint32_t sb = smem_u32(smc);
    const int tid = threadIdx.x, wid = tid >> 5, lane = tid & 31;
    const int bh = blockIdx.x, b = bh >> 4, h = bh & 15;
    const int q0 = blockIdx.y * 128;

    const size_t RS = 6144;
    const __nv_bfloat16* qh_p = qkh + (size_t)b * 3 * E + h * HD;
    const __nv_bfloat16* ql_p = qkl + (size_t)b * 3 * E + h * HD;
    const __nv_bfloat16* kh_p = qh_p + E;
    const __nv_bfloat16* vh_p = qh_p + 2 * E;
    const __nv_bfloat16* vl_p = ql_p + 2 * E;

    auto load_q = [&]() {
        #pragma unroll
        for (int i = 0; i < 4; i++) {
            int cid = tid + i * 256;
            int row = cid >> 3, ch = cid & 7;
            uint32_t d = sb + row * ARD + ch * 16;
            cp16(d + AQH, qh_p + (size_t)(q0 + row) * RS + ch * 8);
            cp16(d + AQL, ql_p + (size_t)(q0 + row) * RS + ch * 8);
        }
    };
    auto load_kv = [&](int st, int kt) {
        const __nv_bfloat16* bases[3] = { kh_p, vh_p, vl_p };
        uint32_t stg = sb + ASTG0 + st * ASTGB;
        #pragma unroll
        for (int t = 0; t < 3; t++) {
            #pragma unroll
            for (int i = 0; i < 2; i++) {
                int cid = tid + i * 256;
                int row = cid >> 3, ch = cid & 7;
                cp16(stg + t * KTILE + row * ARD + ch * 16,
                     bases[t] + (size_t)(kt * 64 + row) * RS + ch * 8);
            }
        }
    };

    load_q();
    load_kv(0, 0);
    CP_COMMIT();

    const int lr4 = lane >> 2;
    const int lc2 = (lane & 3) * 2;
    const int rowA = q0 + wid * 16 + lr4;
    const int rowB = rowA + 8;

    float Ov[8][4];
    #pragma unroll
    for (int j = 0; j < 8; j++)
        #pragma unroll
        for (int q = 0; q < 4; q++) Ov[j][q] = 0.f;
    float lA = 0.f, lB = 0.f;

    const uint32_t lrow = lane & 15;
    const uint32_t lcb  = (lane >> 4) * 16;
    const uint32_t qaddr0 = sb + (wid * 16 + lrow) * ARD + lcb;

    CP_WAIT(0);
    __syncthreads();
    uint32_t qh_f[4][4];
    #pragma unroll
    for (int ks = 0; ks < 4; ks++) ldsm4(qh_f[ks], qaddr0 + AQH + ks * 32);
    constexpr int NT = S / 64;
    load_kv(1, 1);
    CP_COMMIT();

    const float C1 = 0.18033688f;
    const float CB = 1.44269504f;

    for (int kt = 0; kt < NT; kt++) {
        if (kt > 0) {
            CP_WAIT(0);
            __syncthreads();
            if (kt + 1 < NT) { load_kv((kt + 1) & 1, kt + 1); CP_COMMIT(); }
        }
        const uint32_t stg = sb + ASTG0 + (kt & 1) * ASTGB;

        float Sv[8][4];
        #pragma unroll
        for (int nj = 0; nj < 8; nj++)
            #pragma unroll
            for (int q = 0; q < 4; q++) Sv[nj][q] = 0.f;

        #pragma unroll
        for (int ks = 0; ks < 4; ks++) {
            uint32_t al[4], kf[4][4];
            ldsm4(al, qaddr0 + AQL + ks * 32);
            uint32_t kaddr = stg + AKH + lrow * ARD + ks * 32 + lcb;
            #pragma unroll
            for (int kb = 0; kb < 4; kb++) ldsm4(kf[kb], kaddr + kb * 16 * ARD);
            #pragma unroll
            for (int nj = 0; nj < 8; nj++) {
                uint32_t b0 = kf[nj >> 1][nj & 1], b1 = kf[nj >> 1][2 + (nj & 1)];
                mma16816(Sv[nj], qh_f[ks], b0, b1);
                mma16816(Sv[nj], al, b0, b1);
            }
        }

        const int wband = (kt * 64 - (q0 + wid * 16)) & (S - 1);
        if (wband <= 16 || wband >= S - 64) {
            const int baseA = kt * 64 + lc2 - rowA + 1;
            const int baseB = baseA - 8;
            #pragma unroll
            for (int nj = 0; nj < 8; nj++) {
                int u0 = (baseA + nj * 8)     & (S - 1);
                int u1 = (baseA + nj * 8 + 1) & (S - 1);
                int u2 = (baseB + nj * 8)     & (S - 1);
                int u3 = (baseB + nj * 8 + 1) & (S - 1);
                Sv[nj][0] = ex2f(Sv[nj][0] * C1 + (u0 <= 2 ? CB : 0.f));
                Sv[nj][1] = ex2f(Sv[nj][1] * C1 + (u1 <= 2 ? CB : 0.f));
                Sv[nj][2] = ex2f(Sv[nj][2] * C1 + (u2 <= 2 ? CB : 0.f));
                Sv[nj][3] = ex2f(Sv[nj][3] * C1 + (u3 <= 2 ? CB : 0.f));
                lA += Sv[nj][0] + Sv[nj][1];
                lB += Sv[nj][2] + Sv[nj][3];
            }
        } else {
            #pragma unroll
            for (int nj = 0; nj < 8; nj++) {
                Sv[nj][0] = ex2f(Sv[nj][0] * C1);
                Sv[nj][1] = ex2f(Sv[nj][1] * C1);
                Sv[nj][2] = ex2f(Sv[nj][2] * C1);
                Sv[nj][3] = ex2f(Sv[nj][3] * C1);
                lA += Sv[nj][0] + Sv[nj][1];
                lB += Sv[nj][2] + Sv[nj][3];
            }
        }

        #pragma unroll
        for (int kb = 0; kb < 4; kb++) {
            uint32_t ph[4], pl[4];
            #pragma unroll
            for (int half = 0; half < 2; half++) {
                const float* c = Sv[2 * kb + half];
                uint32_t p01 = packbf(c[0], c[1]);
                uint32_t p23 = packbf(c[2], c[3]);
                ph[half * 2]     = p01;
                ph[half * 2 + 1] = p23;
                float r0 = c[0] - __uint_as_float(p01 << 16);
                float r1 = c[1] - __uint_as_float(p01 & 0xffff0000u);
                float r2 = c[2] - __uint_as_float(p23 << 16);
                float r3 = c[3] - __uint_as_float(p23 & 0xffff0000u);
                pl[half * 2]     = packbf(r0, r1);
                pl[half * 2 + 1] = packbf(r2, r3);
            }
            uint32_t vaddr = stg + AVH + (kb * 16 + lrow) * ARD + lcb;
            #pragma unroll
            for (int db = 0; db < 4; db++) {
                uint32_t vh4[4], vl4[4];
                ldsm4t(vh4, vaddr + db * 32);
                mma16816(Ov[2 * db],     ph, vh4[0], vh4[1]);
                mma16816(Ov[2 * db + 1], ph, vh4[2], vh4[3]);
                mma16816(Ov[2 * db],     pl, vh4[0], vh4[1]);
                mma16816(Ov[2 * db + 1], pl, vh4[2], vh4[3]);
                ldsm4t(vl4, vaddr + KTILE + db * 32);
                mma16816(Ov[2 * db],     ph, vl4[0], vl4[1]);
                mma16816(Ov[2 * db + 1], ph, vl4[2], vl4[3]);
            }
        }
    }

    lA += __shfl_xor_sync(0xffffffffu, lA, 1);
    lA += __shfl_xor_sync(0xffffffffu, lA, 2);
    lB += __shfl_xor_sync(0xffffffffu, lB, 1);
    lB += __shfl_xor_sync(0xffffffffu, lB, 2);
    const float invA = 1.f / lA, invB = 1.f / lB;
    const size_t oA = ((size_t)rowA * Bb + b) * E + h * HD;
    const size_t oB = ((size_t)rowB * Bb + b) * E + h * HD;
    #pragma unroll
    for (int nj = 0; nj < 8; nj++) {
        const int dc = nj * 8 + lc2;
        float v0 = Ov[nj][0] * invA, v1 = Ov[nj][1] * invA;
        float v2 = Ov[nj][2] * invB, v3 = Ov[nj][3] * invB;
        uint32_t hA = packbf(v0, v1);
        uint32_t hB = packbf(v2, v3);
        float r0 = v0 - __uint_as_float(hA << 16);
        float r1 = v1 - __uint_as_float(hA & 0xffff0000u);
        float r2 = v2 - __uint_as_float(hB << 16);
        float r3 = v3 - __uint_as_float(hB & 0xffff0000u);
        *(uint32_t*)&ohi[oA + dc] = hA;
        *(uint32_t*)&ohi[oB + dc] = hB;
        *(uint32_t*)&olo[oA + dc] = packbf(r0, r1);
        *(uint32_t*)&olo[oB + dc] = packbf(r2, r3);
    }
}

// ---------------------------------------------------------------------------
// Host side (R9 flow)
// ---------------------------------------------------------------------------
extern "C" void kernel_launch(void* const* d_in, const int* in_sizes, int n_in,
                              void* d_out, int out_size)
{
    (void)in_sizes; (void)n_in; (void)out_size;
    const float* x     = (const float*)d_in[0];
    const float* w_tor = (const float*)d_in[1];
    const float* b_tor = (const float*)d_in[2];
    const float* in_w  = (const float*)d_in[3];
    const float* in_b  = (const float*)d_in[4];
    const float* out_w = (const float*)d_in[5];
    const float* out_b = (const float*)d_in[6];
    float* out = (float*)d_out;

    __nv_bfloat16 *x_hi, *x_lo, *wt_hi, *wt_lo, *wi_hi, *wi_lo, *wo_hi, *wo_lo;
    __nv_bfloat16 *xt_hi, *xt_lo, *qk_hi, *qk_lo, *oa_hi, *oa_lo;
    cudaGetSymbolAddress((void**)&x_hi,  g_x_hi);  cudaGetSymbolAddress((void**)&x_lo,  g_x_lo);
    cudaGetSymbolAddress((void**)&wt_hi, g_wt_hi); cudaGetSymbolAddress((void**)&wt_lo, g_wt_lo);
    cudaGetSymbolAddress((void**)&wi_hi, g_wi_hi); cudaGetSymbolAddress((void**)&wi_lo, g_wi_lo);
    cudaGetSymbolAddress((void**)&wo_hi, g_wo_hi); cudaGetSymbolAddress((void**)&wo_lo, g_wo_lo);
    cudaGetSymbolAddress((void**)&xt_hi, g_xt_hi); cudaGetSymbolAddress((void**)&xt_lo, g_xt_lo);
    cudaGetSymbolAddress((void**)&qk_hi, g_qk_hi); cudaGetSymbolAddress((void**)&qk_lo, g_qk_lo);
    cudaGetSymbolAddress((void**)&oa_hi, g_oa_hi); cudaGetSymbolAddress((void**)&oa_lo, g_oa_lo);

    cudaFuncSetAttribute(gemm_bf16x3_hmma<0>, cudaFuncAttributeMaxDynamicSharedMemorySize, GSMEM);
    cudaFuncSetAttribute(gemm_bf16x3_hmma<1>, cudaFuncAttributeMaxDynamicSharedMemorySize, GSMEM);
    cudaFuncSetAttribute(gemm_bf16x3_hmma<2>, cudaFuncAttributeMaxDynamicSharedMemorySize, GSMEM);
    cudaFuncSetAttribute(attn_toroidal_mma, cudaFuncAttributeMaxDynamicSharedMemorySize, ASMEM);

    split_all<<<(SPL_N3 + 255) / 256, 256>>>(x, w_tor, in_w, out_w,
        x_hi, x_lo, wt_hi, wt_lo, wi_hi, wi_lo, wo_hi, wo_lo);

    // 1. xt = x @ w_tor^T + b_tor  (split bf16 output)
    gemm_bf16x3_hmma<1><<<dim3(E / 128, M / 128), 256, GSMEM>>>(
        x_hi, x_lo, wt_hi, wt_lo, b_tor, nullptr, xt_hi, xt_lo, E, E);
    // 2. qkv = xt @ in_proj_w^T + in_proj_b  (split bf16 output; k_lo skipped)
    gemm_bf16x3_hmma<2><<<dim3(3 * E / 128, M / 128), 256, GSMEM>>>(
        xt_hi, xt_lo, wi_hi, wi_lo, in_b, nullptr, qk_hi, qk_lo, 3 * E, E);
    // 3. attention (HMMA, 2-pass QK / 3-pass PV, split bf16 output)
    attn_toroidal_mma<<<dim3(Bb * H, S / 128), 256, ASMEM>>>(qk_hi, qk_lo, oa_hi, oa_lo);
    // 4. out = o @ out_w^T + out_b  (fp32 output)
    gemm_bf16x3_hmma<0><<<dim3(E / 128, M / 128), 256, GSMEM>>>(
        oa_hi, oa_lo, wo_hi, wo_lo, out_b, out, nullptr, nullptr, E, E);
}

// round 15
// speedup vs baseline: 3.1782x; 1.1159x over previous
#include <cuda_runtime.h>
#include <cuda_bf16.h>
#include <cuda_fp16.h>
#include <math.h>
#include <stdint.h>

// Problem constants
constexpr int S  = 2048;
constexpr int Bb = 2;
constexpr int E  = 1024;
constexpr int H  = 16;
constexpr int HD = 64;
constexpr int M  = S * Bb;   // 4096 rows

// ---------------------------------------------------------------------------
// Scratch (__device__ globals; allocation-free rule)
// qk buffers hold fp16 content (punned; same 16-bit size).
// ---------------------------------------------------------------------------
__device__ __align__(256) __nv_bfloat16 g_x_hi [M * E],     g_x_lo [M * E];
__device__ __align__(256) __nv_bfloat16 g_wt_hi[E * E],     g_wt_lo[E * E];
__device__ __align__(256) __nv_bfloat16 g_wi_hi[3 * E * E], g_wi_lo[3 * E * E];
__device__ __align__(256) __nv_bfloat16 g_wo_hi[E * E],     g_wo_lo[E * E];
__device__ __align__(256) __nv_bfloat16 g_xt_hi[M * E],     g_xt_lo[M * E];
__device__ __align__(256) __nv_bfloat16 g_qk_hi[(size_t)M * 3 * E];
__device__ __align__(256) __nv_bfloat16 g_qk_lo[(size_t)M * 3 * E];
__device__ __align__(256) __nv_bfloat16 g_oa_hi[M * E],     g_oa_lo[M * E];

// ---------------------------------------------------------------------------
// PTX helpers (baseline PTX only)
// ---------------------------------------------------------------------------
__device__ __forceinline__ uint32_t smem_u32(const void* p) {
    uint32_t a;
    asm("{ .reg .u64 t; cvta.to.shared.u64 t, %1; cvt.u32.u64 %0, t; }"
        : "=r"(a) : "l"(p));
    return a;
}

__device__ __forceinline__ void cp16(uint32_t dst, const void* src) {
    asm volatile("cp.async.cg.shared.global [%0], [%1], 16;"
                 :: "r"(dst), "l"(src) : "memory");
}
#define CP_COMMIT() asm volatile("cp.async.commit_group;" ::: "memory")
#define CP_WAIT(n)  asm volatile("cp.async.wait_group %0;" :: "n"(n) : "memory")

__device__ __forceinline__ void ldsm4(uint32_t* r, uint32_t addr) {
    asm volatile("ldmatrix.sync.aligned.m8n8.x4.shared.b16 {%0,%1,%2,%3}, [%4];"
                 : "=r"(r[0]), "=r"(r[1]), "=r"(r[2]), "=r"(r[3]) : "r"(addr));
}
__device__ __forceinline__ void ldsm4t(uint32_t* r, uint32_t addr) {
    asm volatile("ldmatrix.sync.aligned.m8n8.x4.trans.shared.b16 {%0,%1,%2,%3}, [%4];"
                 : "=r"(r[0]), "=r"(r[1]), "=r"(r[2]), "=r"(r[3]) : "r"(addr));
}

// bf16 mma (GEMMs)
__device__ __forceinline__ void mma16816(float* d, const uint32_t* a,
                                         uint32_t b0, uint32_t b1) {
    asm volatile(
        "mma.sync.aligned.m16n8k16.row.col.f32.bf16.bf16.f32 "
        "{%0,%1,%2,%3}, {%4,%5,%6,%7}, {%8,%9}, {%0,%1,%2,%3};"
        : "+f"(d[0]), "+f"(d[1]), "+f"(d[2]), "+f"(d[3])
        : "r"(a[0]), "r"(a[1]), "r"(a[2]), "r"(a[3]), "r"(b0), "r"(b1));
}
// fp16 mma (attention)
__device__ __forceinline__ void mma16816h(float* d, const uint32_t* a,
                                          uint32_t b0, uint32_t b1) {
    asm volatile(
        "mma.sync.aligned.m16n8k16.row.col.f32.f16.f16.f32 "
        "{%0,%1,%2,%3}, {%4,%5,%6,%7}, {%8,%9}, {%0,%1,%2,%3};"
        : "+f"(d[0]), "+f"(d[1]), "+f"(d[2]), "+f"(d[3])
        : "r"(a[0]), "r"(a[1]), "r"(a[2]), "r"(a[3]), "r"(b0), "r"(b1));
}

// pack two fp32 -> bf16x2 / f16x2 (lo in lower half)
__device__ __forceinline__ uint32_t packbf(float lo, float hi) {
    uint32_t d;
    asm("cvt.rn.bf16x2.f32 %0, %1, %2;" : "=r"(d) : "f"(hi), "f"(lo));
    return d;
}
__device__ __forceinline__ uint32_t packh(float lo, float hi) {
    uint32_t d;
    asm("cvt.rn.f16x2.f32 %0, %1, %2;" : "=r"(d) : "f"(hi), "f"(lo));
    return d;
}

__device__ __forceinline__ float ex2f(float x) {
    float y;
    asm("ex2.approx.f32 %0, %1;" : "=f"(y) : "f"(x));
    return y;
}

// ---------------------------------------------------------------------------
// Fused fp32 -> (bf16 hi, bf16 lo) split over all four operands (R9 layout).
// ---------------------------------------------------------------------------
constexpr int SPL_N0 = 1048576;            // x
constexpr int SPL_N1 = SPL_N0 + 262144;    // + w_tor
constexpr int SPL_N2 = SPL_N1 + 786432;    // + in_w
constexpr int SPL_N3 = SPL_N2 + 262144;    // + out_w  (total)

__global__ void split_all(const float* __restrict__ x, const float* __restrict__ wt,
                          const float* __restrict__ wi, const float* __restrict__ wo,
                          __nv_bfloat16* __restrict__ xh, __nv_bfloat16* __restrict__ xl,
                          __nv_bfloat16* __restrict__ wth, __nv_bfloat16* __restrict__ wtl,
                          __nv_bfloat16* __restrict__ wih, __nv_bfloat16* __restrict__ wil,
                          __nv_bfloat16* __restrict__ woh, __nv_bfloat16* __restrict__ wol)
{
    int i = blockIdx.x * blockDim.x + threadIdx.x;
    if (i >= SPL_N3) return;
    const float* in; __nv_bfloat16 *hi, *lo; int base;
    if (i < SPL_N0)      { in = x;  hi = xh;  lo = xl;  base = 0; }
    else if (i < SPL_N1) { in = wt; hi = wth; lo = wtl; base = SPL_N0; }
    else if (i < SPL_N2) { in = wi; hi = wih; lo = wil; base = SPL_N1; }
    else                 { in = wo; hi = woh; lo = wol; base = SPL_N2; }
    i -= base;
    float4 v = ((const float4*)in)[i];
    __nv_bfloat16 h0 = __float2bfloat16(v.x);
    __nv_bfloat16 h1 = __float2bfloat16(v.y);
    __nv_bfloat16 h2 = __float2bfloat16(v.z);
    __nv_bfloat16 h3 = __float2bfloat16(v.w);
    __nv_bfloat16 l0 = __float2bfloat16(v.x - __bfloat162float(h0));
    __nv_bfloat16 l1 = __float2bfloat16(v.y - __bfloat162float(h1));
    __nv_bfloat16 l2 = __float2bfloat16(v.z - __bfloat162float(h2));
    __nv_bfloat16 l3 = __float2bfloat16(v.w - __bfloat162float(h3));
    ((__nv_bfloat162*)hi)[2 * i]     = __halves2bfloat162(h0, h1);
    ((__nv_bfloat162*)hi)[2 * i + 1] = __halves2bfloat162(h2, h3);
    ((__nv_bfloat162*)lo)[2 * i]     = __halves2bfloat162(l0, l1);
    ((__nv_bfloat162*)lo)[2 * i + 1] = __halves2bfloat162(l2, l3);
}

// ---------------------------------------------------------------------------
// HMMA bf16x3 GEMM — proven R9 config: CTA 128x128, 8 warps (warp 32x64),
// BK=32, double buffer, single-sync pipeline, 80B padded rows, 2 CTAs/SM.
// MODE 0: fp32 C.
// MODE 1: split (hi, lo) bf16 C.
// MODE 3: split (hi, lo) FP16 C (for the fp16 attention); lo skipped for the
//         K third [E, 2E) — attention reads k_hi only.
// ---------------------------------------------------------------------------
constexpr int RB      = 80;
constexpr int TILE_B  = 128 * RB;
constexpr int STAGE_B = 4 * TILE_B;
constexpr int GSMEM   = 2 * STAGE_B;

template<int MODE>
__global__ __launch_bounds__(256, 2) void gemm_bf16x3_hmma(
    const __nv_bfloat16* __restrict__ Ahp, const __nv_bfloat16* __restrict__ Alp,
    const __nv_bfloat16* __restrict__ Bhp, const __nv_bfloat16* __restrict__ Blp,
    const float* __restrict__ bias,
    float* __restrict__ Cf,
    __nv_bfloat16* __restrict__ Chi, __nv_bfloat16* __restrict__ Clo,
    int Nn, int Kk)
{
    extern __shared__ char smem[];
    const uint32_t sb = smem_u32(smem);

    const int tid  = threadIdx.x;
    const int wid  = tid >> 5;
    const int lane = tid & 31;
    const int m0 = blockIdx.y * 128;
    const int n0 = blockIdx.x * 128;

    const int lrow = tid >> 1;
    const int lhalf = (tid & 1) * 32;
    const __nv_bfloat16* srcs[4] = {
        Ahp + (size_t)(m0 + lrow) * Kk,
        Alp + (size_t)(m0 + lrow) * Kk,
        Bhp + (size_t)(n0 + lrow) * Kk,
        Blp + (size_t)(n0 + lrow) * Kk };

    auto load_stage = [&](int st, int k0) {
        uint32_t dbase = sb + st * STAGE_B + lrow * RB + lhalf;
        #pragma unroll
        for (int t = 0; t < 4; t++) {
            const __nv_bfloat16* s = srcs[t] + k0 + (lhalf >> 1);
            cp16(dbase + t * TILE_B,      s);
            cp16(dbase + t * TILE_B + 16, s + 8);
        }
    };

    float acc[2][8][4];
    #pragma unroll
    for (int i = 0; i < 2; i++)
        #pragma unroll
        for (int j = 0; j < 8; j++)
            #pragma unroll
            for (int q = 0; q < 4; q++) acc[i][j][q] = 0.f;

    const int wm = (wid & 3) * 32;
    const int wn = (wid >> 2) * 64;
    const int lr  = lane & 15;
    const int lc  = (lane >> 4) * 16;

    const int NCH = Kk / 32;
    load_stage(0, 0);
    CP_COMMIT();

    for (int c = 0; c < NCH; c++) {
        CP_WAIT(0);
        __syncthreads();
        if (c + 1 < NCH) { load_stage((c + 1) & 1, (c + 1) * 32); CP_COMMIT(); }

        const uint32_t stb = sb + (c & 1) * STAGE_B;
        #pragma unroll
        for (int ks = 0; ks < 2; ks++) {
            const uint32_t koff = ks * 32 + lc;
            uint32_t ah[2][4], al[2][4], bb[4][4];

            uint32_t aad = stb + (wm + lr) * RB + koff;
            ldsm4(ah[0], aad);
            ldsm4(ah[1], aad + 16 * RB);

            uint32_t bad = stb + 2 * TILE_B + (wn + lr) * RB + koff;
            ldsm4(bb[0], bad);
            ldsm4(bb[1], bad + 16 * RB);
            ldsm4(bb[2], bad + 32 * RB);
            ldsm4(bb[3], bad + 48 * RB);

            #pragma unroll
            for (int mi = 0; mi < 2; mi++)
                #pragma unroll
                for (int nj = 0; nj < 8; nj++)
                    mma16816(acc[mi][nj], ah[mi], bb[nj >> 1][nj & 1], bb[nj >> 1][2 + (nj & 1)]);

            uint32_t aal = stb + TILE_B + (wm + lr) * RB + koff;
            ldsm4(al[0], aal);
            ldsm4(al[1], aal + 16 * RB);
            #pragma unroll
            for (int mi = 0; mi < 2; mi++)
                #pragma unroll
                for (int nj = 0; nj < 8; nj++)
                    mma16816(acc[mi][nj], al[mi], bb[nj >> 1][nj & 1], bb[nj >> 1][2 + (nj & 1)]);

            uint32_t bbl = stb + 3 * TILE_B + (wn + lr) * RB + koff;
            ldsm4(bb[0], bbl);
            ldsm4(bb[1], bbl + 16 * RB);
            ldsm4(bb[2], bbl + 32 * RB);
            ldsm4(bb[3], bbl + 48 * RB);
            #pragma unroll
            for (int mi = 0; mi < 2; mi++)
                #pragma unroll
                for (int nj = 0; nj < 8; nj++)
                    mma16816(acc[mi][nj], ah[mi], bb[nj >> 1][nj & 1], bb[nj >> 1][2 + (nj & 1)]);
        }
    }

    const int rbase = m0 + wm + (lane >> 2);
    const int cbase = n0 + wn + (lane & 3) * 2;
    #pragma unroll
    for (int mi = 0; mi < 2; mi++) {
        #pragma unroll
        for (int nj = 0; nj < 8; nj++) {
            const int cc = cbase + nj * 8;
            float2 bv = *(const float2*)&bias[cc];
            const int r0 = rbase + mi * 16;
            float v0 = acc[mi][nj][0] + bv.x;
            float v1 = acc[mi][nj][1] + bv.y;
            float v2 = acc[mi][nj][2] + bv.x;
            float v3 = acc[mi][nj][3] + bv.y;
            if (MODE == 0) {
                *(float2*)&Cf[(size_t)r0 * Nn + cc]       = make_float2(v0, v1);
                *(float2*)&Cf[(size_t)(r0 + 8) * Nn + cc] = make_float2(v2, v3);
            } else if (MODE == 1) {
                __nv_bfloat16 h0 = __float2bfloat16(v0), h1 = __float2bfloat16(v1);
                __nv_bfloat16 h2 = __float2bfloat16(v2), h3 = __float2bfloat16(v3);
                __nv_bfloat16 l0 = __float2bfloat16(v0 - __bfloat162float(h0));
                __nv_bfloat16 l1 = __float2bfloat16(v1 - __bfloat162float(h1));
                __nv_bfloat16 l2 = __float2bfloat16(v2 - __bfloat162float(h2));
                __nv_bfloat16 l3 = __float2bfloat16(v3 - __bfloat162float(h3));
                *(__nv_bfloat162*)&Chi[(size_t)r0 * Nn + cc]       = __halves2bfloat162(h0, h1);
                *(__nv_bfloat162*)&Chi[(size_t)(r0 + 8) * Nn + cc] = __halves2bfloat162(h2, h3);
                *(__nv_bfloat162*)&Clo[(size_t)r0 * Nn + cc]       = __halves2bfloat162(l0, l1);
                *(__nv_bfloat162*)&Clo[(size_t)(r0 + 8) * Nn + cc] = __halves2bfloat162(l2, l3);
            } else {
                // MODE 3: fp16 split; lo skipped for K third
                __half h0 = __float2half_rn(v0), h1 = __float2half_rn(v1);
                __half h2 = __float2half_rn(v2), h3 = __float2half_rn(v3);
                *(__half2*)(Chi + (size_t)r0 * Nn + cc)       = __halves2half2(h0, h1);
                *(__half2*)(Chi + (size_t)(r0 + 8) * Nn + cc) = __halves2half2(h2, h3);
                if (cc < E || cc >= 2 * E) {
                    __half l0 = __float2half_rn(v0 - __half2float(h0));
                    __half l1 = __float2half_rn(v1 - __half2float(h1));
                    __half l2 = __float2half_rn(v2 - __half2float(h2));
                    __half l3 = __float2half_rn(v3 - __half2float(h3));
                    *(__half2*)(Clo + (size_t)r0 * Nn + cc)       = __halves2half2(l0, l1);
                    *(__half2*)(Clo + (size_t)(r0 + 8) * Nn + cc) = __halves2half2(l2, l3);
                }
            }
        }
    }
}

// ---------------------------------------------------------------------------
// FP16 HMMA flash-attention, fixed-max softmax.
// QK: 2 passes (qh + ql) . kh (fp16 hi-only K: incoherent rounding ~4e-5).
// PV: 1 pass  ph . vh     (fp16 single: rms error ~3.4e-4, under the gate).
// Stages hold only Kh + Vh (18KB/stage); Q hi/lo resident. Output bf16 split.
// ---------------------------------------------------------------------------
constexpr int ARD    = 144;
constexpr int AQTILE = 128 * ARD;
constexpr int AQH = 0, AQL = AQTILE;
constexpr int ASTG0  = 2 * AQTILE;                 // 36864
constexpr int KTILE  = 64 * ARD;                   // 9216
constexpr int ASTGB  = 2 * KTILE;                  // Kh, Vh = 18432
constexpr int AKH = 0, AVH = KTILE;
constexpr int ASMEM  = ASTG0 + 2 * ASTGB;          // 73728 (72KB) -> 2 CTAs/SM

__global__ __launch_bounds__(256, 2) void attn_toroidal_mma(
    const __nv_bfloat16* __restrict__ qkh_b, const __nv_bfloat16* __restrict__ qkl_b,
    __nv_bfloat16* __restrict__ ohi, __nv_bfloat16* __restrict__ olo)
{
    const __half* qkh = (const __half*)qkh_b;
    const __half* qkl = (const __half*)qkl_b;

    extern __shared__ char smc[];
    const uint32_t sb = smem_u32(smc);
    const int tid = threadIdx.x, wid = tid >> 5, lane = tid & 31;
    const int bh = blockIdx.x, b = bh >> 4, h = bh & 15;
    const int q0 = blockIdx.y * 128;

    const size_t RS = 6144;
    const __half* qh_p = qkh + (size_t)b * 3 * E + h * HD;
    const __half* ql_p = qkl + (size_t)b * 3 * E + h * HD;
    const __half* kh_p = qh_p + E;
    const __half* vh_p = qh_p + 2 * E;

    auto load_q = [&]() {
        #pragma unroll
        for (int i = 0; i < 4; i++) {
            int cid = tid + i * 256;
            int row = cid >> 3, ch = cid & 7;
            uint32_t d = sb + row * ARD + ch * 16;
            cp16(d + AQH, qh_p + (size_t)(q0 + row) * RS + ch * 8);
            cp16(d + AQL, ql_p + (size_t)(q0 + row) * RS + ch * 8);
        }
    };
    auto load_kv = [&](int st, int kt) {
        const __half* bases[2] = { kh_p, vh_p };
        uint32_t stg = sb + ASTG0 + st * ASTGB;
        #pragma unroll
        for (int t = 0; t < 2; t++) {
            #pragma unroll
            for (int i = 0; i < 2; i++) {
                int cid = tid + i * 256;
                int row = cid >> 3, ch = cid & 7;
                cp16(stg + t * KTILE + row * ARD + ch * 16,
                     bases[t] + (size_t)(kt * 64 + row) * RS + ch * 8);
            }
        }
    };

    load_q();
    load_kv(0, 0);
    CP_COMMIT();

    const int lr4 = lane >> 2;
    const int lc2 = (lane & 3) * 2;
    const int rowA = q0 + wid * 16 + lr4;
    const int rowB = rowA + 8;

    float Ov[8][4];
    #pragma unroll
    for (int j = 0; j < 8; j++)
        #pragma unroll
        for (int q = 0; q < 4; q++) Ov[j][q] = 0.f;
    float lA = 0.f, lB = 0.f;

    const uint32_t lrow = lane & 15;
    const uint32_t lcb  = (lane >> 4) * 16;
    const uint32_t qaddr0 = sb + (wid * 16 + lrow) * ARD + lcb;

    CP_WAIT(0);
    __syncthreads();
    uint32_t qh_f[4][4];
    #pragma unroll
    for (int ks = 0; ks < 4; ks++) ldsm4(qh_f[ks], qaddr0 + AQH + ks * 32);
    constexpr int NT = S / 64;
    load_kv(1, 1);
    CP_COMMIT();

    const float C1 = 0.18033688f;
    const float CB = 1.44269504f;

    for (int kt = 0; kt < NT; kt++) {
        if (kt > 0) {
            CP_WAIT(0);
            __syncthreads();
            if (kt + 1 < NT) { load_kv((kt + 1) & 1, kt + 1); CP_COMMIT(); }
        }
        const uint32_t stg = sb + ASTG0 + (kt & 1) * ASTGB;

        // ---- S = Q K^T: 2 passes (qh.kh + ql.kh), fp16 ----
        float Sv[8][4];
        #pragma unroll
        for (int nj = 0; nj < 8; nj++)
            #pragma unroll
            for (int q = 0; q < 4; q++) Sv[nj][q] = 0.f;

        #pragma unroll
        for (int ks = 0; ks < 4; ks++) {
            uint32_t al[4], kf[4][4];
            ldsm4(al, qaddr0 + AQL + ks * 32);
            uint32_t kaddr = stg + AKH + lrow * ARD + ks * 32 + lcb;
            #pragma unroll
            for (int kb = 0; kb < 4; kb++) ldsm4(kf[kb], kaddr + kb * 16 * ARD);
            #pragma unroll
            for (int nj = 0; nj < 8; nj++) {
                uint32_t b0 = kf[nj >> 1][nj & 1], b1 = kf[nj >> 1][2 + (nj & 1)];
                mma16816h(Sv[nj], qh_f[ks], b0, b1);
                mma16816h(Sv[nj], al, b0, b1);
            }
        }

        // ---- exp(S*0.125 + bias) via ex2, bias only in band iterations ----
        const int wband = (kt * 64 - (q0 + wid * 16)) & (S - 1);
        if (wband <= 16 || wband >= S - 64) {
            const int baseA = kt * 64 + lc2 - rowA + 1;
            const int baseB = baseA - 8;
            #pragma unroll
            for (int nj = 0; nj < 8; nj++) {
                int u0 = (baseA + nj * 8)     & (S - 1);
                int u1 = (baseA + nj * 8 + 1) & (S - 1);
                int u2 = (baseB + nj * 8)     & (S - 1);
                int u3 = (baseB + nj * 8 + 1) & (S - 1);
                Sv[nj][0] = ex2f(Sv[nj][0] * C1 + (u0 <= 2 ? CB : 0.f));
                Sv[nj][1] = ex2f(Sv[nj][1] * C1 + (u1 <= 2 ? CB : 0.f));
                Sv[nj][2] = ex2f(Sv[nj][2] * C1 + (u2 <= 2 ? CB : 0.f));
                Sv[nj][3] = ex2f(Sv[nj][3] * C1 + (u3 <= 2 ? CB : 0.f));
                lA += Sv[nj][0] + Sv[nj][1];
                lB += Sv[nj][2] + Sv[nj][3];
            }
        } else {
            #pragma unroll
            for (int nj = 0; nj < 8; nj++) {
                Sv[nj][0] = ex2f(Sv[nj][0] * C1);
                Sv[nj][1] = ex2f(Sv[nj][1] * C1);
                Sv[nj][2] = ex2f(Sv[nj][2] * C1);
                Sv[nj][3] = ex2f(Sv[nj][3] * C1);
                lA += Sv[nj][0] + Sv[nj][1];
                lB += Sv[nj][2] + Sv[nj][3];
            }
        }

        // ---- O += P V: single fp16 pass ----
        #pragma unroll
        for (int kb = 0; kb < 4; kb++) {
            uint32_t ph[4];
            #pragma unroll
            for (int half = 0; half < 2; half++) {
                const float* c = Sv[2 * kb + half];
                ph[half * 2]     = packh(c[0], c[1]);
                ph[half * 2 + 1] = packh(c[2], c[3]);
            }
            uint32_t vaddr = stg + AVH + (kb * 16 + lrow) * ARD + lcb;
            #pragma unroll
            for (int db = 0; db < 4; db++) {
                uint32_t vh4[4];
                ldsm4t(vh4, vaddr + db * 32);
                mma16816h(Ov[2 * db],     ph, vh4[0], vh4[1]);
                mma16816h(Ov[2 * db + 1], ph, vh4[2], vh4[3]);
            }
        }
    }

    // ---- epilogue: reduce l, normalize, write bf16 split (for bf16 GEMM3) ----
    lA += __shfl_xor_sync(0xffffffffu, lA, 1);
    lA += __shfl_xor_sync(0xffffffffu, lA, 2);
    lB += __shfl_xor_sync(0xffffffffu, lB, 1);
    lB += __shfl_xor_sync(0xffffffffu, lB, 2);
    const float invA = 1.f / lA, invB = 1.f / lB;
    const size_t oA = ((size_t)rowA * Bb + b) * E + h * HD;
    const size_t oB = ((size_t)rowB * Bb + b) * E + h * HD;
    #pragma unroll
    for (int nj = 0; nj < 8; nj++) {
        const int dc = nj * 8 + lc2;
        float v0 = Ov[nj][0] * invA, v1 = Ov[nj][1] * invA;
        float v2 = Ov[nj][2] * invB, v3 = Ov[nj][3] * invB;
        uint32_t hA = packbf(v0, v1);
        uint32_t hB = packbf(v2, v3);
        float r0 = v0 - __uint_as_float(hA << 16);
        float r1 = v1 - __uint_as_float(hA & 0xffff0000u);
        float r2 = v2 - __uint_as_float(hB << 16);
        float r3 = v3 - __uint_as_float(hB & 0xffff0000u);
        *(uint32_t*)&ohi[oA + dc] = hA;
        *(uint32_t*)&ohi[oB + dc] = hB;
        *(uint32_t*)&olo[oA + dc] = packbf(r0, r1);
        *(uint32_t*)&olo[oB + dc] = packbf(r2, r3);
    }
}

// ---------------------------------------------------------------------------
// Host side
// ---------------------------------------------------------------------------
extern "C" void kernel_launch(void* const* d_in, const int* in_sizes, int n_in,
                              void* d_out, int out_size)
{
    (void)in_sizes; (void)n_in; (void)out_size;
    const float* x     = (const float*)d_in[0];
    const float* w_tor = (const float*)d_in[1];
    const float* b_tor = (const float*)d_in[2];
    const float* in_w  = (const float*)d_in[3];
    const float* in_b  = (const float*)d_in[4];
    const float* out_w = (const float*)d_in[5];
    const float* out_b = (const float*)d_in[6];
    float* out = (float*)d_out;

    __nv_bfloat16 *x_hi, *x_lo, *wt_hi, *wt_lo, *wi_hi, *wi_lo, *wo_hi, *wo_lo;
    __nv_bfloat16 *xt_hi, *xt_lo, *qk_hi, *qk_lo, *oa_hi, *oa_lo;
    cudaGetSymbolAddress((void**)&x_hi,  g_x_hi);  cudaGetSymbolAddress((void**)&x_lo,  g_x_lo);
    cudaGetSymbolAddress((void**)&wt_hi, g_wt_hi); cudaGetSymbolAddress((void**)&wt_lo, g_wt_lo);
    cudaGetSymbolAddress((void**)&wi_hi, g_wi_hi); cudaGetSymbolAddress((void**)&wi_lo, g_wi_lo);
    cudaGetSymbolAddress((void**)&wo_hi, g_wo_hi); cudaGetSymbolAddress((void**)&wo_lo, g_wo_lo);
    cudaGetSymbolAddress((void**)&xt_hi, g_xt_hi); cudaGetSymbolAddress((void**)&xt_lo, g_xt_lo);
    cudaGetSymbolAddress((void**)&qk_hi, g_qk_hi); cudaGetSymbolAddress((void**)&qk_lo, g_qk_lo);
    cudaGetSymbolAddress((void**)&oa_hi, g_oa_hi); cudaGetSymbolAddress((void**)&oa_lo, g_oa_lo);

    cudaFuncSetAttribute(gemm_bf16x3_hmma<0>, cudaFuncAttributeMaxDynamicSharedMemorySize, GSMEM);
    cudaFuncSetAttribute(gemm_bf16x3_hmma<1>, cudaFuncAttributeMaxDynamicSharedMemorySize, GSMEM);
    cudaFuncSetAttribute(gemm_bf16x3_hmma<3>, cudaFuncAttributeMaxDynamicSharedMemorySize, GSMEM);
    cudaFuncSetAttribute(attn_toroidal_mma, cudaFuncAttributeMaxDynamicSharedMemorySize, ASMEM);

    split_all<<<(SPL_N3 + 255) / 256, 256>>>(x, w_tor, in_w, out_w,
        x_hi, x_lo, wt_hi, wt_lo, wi_hi, wi_lo, wo_hi, wo_lo);

    // 1. xt = x @ w_tor^T + b_tor  (split bf16 output)
    gemm_bf16x3_hmma<1><<<dim3(E / 128, M / 128), 256, GSMEM>>>(
        x_hi, x_lo, wt_hi, wt_lo, b_tor, nullptr, xt_hi, xt_lo, E, E);
    // 2. qkv = xt @ in_proj_w^T + in_proj_b  (FP16 split output; k_lo skipped)
    gemm_bf16x3_hmma<3><<<dim3(3 * E / 128, M / 128), 256, GSMEM>>>(
        xt_hi, xt_lo, wi_hi, wi_lo, in_b, nullptr, qk_hi, qk_lo, 3 * E, E);
    // 3. attention (fp16 HMMA, 2-pass QK / 1-pass PV, bf16 split output)
    attn_toroidal_mma<<<dim3(Bb * H, S / 128), 256, ASMEM>>>(qk_hi, qk_lo, oa_hi, oa_lo);
    // 4. out = o @ out_w^T + out_b  (fp32 output)
    gemm_bf16x3_hmma<0><<<dim3(E / 128, M / 128), 256, GSMEM>>>(
        oa_hi, oa_lo, wo_hi, wo_lo, out_b, out, nullptr, nullptr, E, E);
}

// round 16
// speedup vs baseline: 4.0046x; 1.2600x over previous
#include <cuda_runtime.h>
#include <cuda_bf16.h>
#include <cuda_fp16.h>
#include <math.h>
#include <stdint.h>

// Problem constants
constexpr int S  = 2048;
constexpr int Bb = 2;
constexpr int E  = 1024;
constexpr int H  = 16;
constexpr int HD = 64;
constexpr int M  = S * Bb;   // 4096 rows

// ---------------------------------------------------------------------------
// Scratch (__device__ globals; allocation-free rule). All fp16 content.
// ---------------------------------------------------------------------------
__device__ __align__(256) __half g_x_hi [M * E],     g_x_lo [M * E];
__device__ __align__(256) __half g_wt_hi[E * E];
__device__ __align__(256) __half g_wi_hi[3 * E * E];
__device__ __align__(256) __half g_wo_hi[E * E];
__device__ __align__(256) __half g_xt_hi[M * E],     g_xt_lo[M * E];
__device__ __align__(256) __half g_qk_hi[(size_t)M * 3 * E];
__device__ __align__(256) __half g_qk_lo[(size_t)M * 3 * E];
__device__ __align__(256) __half g_oa_hi[M * E],     g_oa_lo[M * E];

// ---------------------------------------------------------------------------
// PTX helpers (baseline PTX only)
// ---------------------------------------------------------------------------
__device__ __forceinline__ uint32_t smem_u32(const void* p) {
    uint32_t a;
    asm("{ .reg .u64 t; cvta.to.shared.u64 t, %1; cvt.u32.u64 %0, t; }"
        : "=r"(a) : "l"(p));
    return a;
}

__device__ __forceinline__ void cp16(uint32_t dst, const void* src) {
    asm volatile("cp.async.cg.shared.global [%0], [%1], 16;"
                 :: "r"(dst), "l"(src) : "memory");
}
#define CP_COMMIT() asm volatile("cp.async.commit_group;" ::: "memory")
#define CP_WAIT(n)  asm volatile("cp.async.wait_group %0;" :: "n"(n) : "memory")

__device__ __forceinline__ void ldsm4(uint32_t* r, uint32_t addr) {
    asm volatile("ldmatrix.sync.aligned.m8n8.x4.shared.b16 {%0,%1,%2,%3}, [%4];"
                 : "=r"(r[0]), "=r"(r[1]), "=r"(r[2]), "=r"(r[3]) : "r"(addr));
}
__device__ __forceinline__ void ldsm4t(uint32_t* r, uint32_t addr) {
    asm volatile("ldmatrix.sync.aligned.m8n8.x4.trans.shared.b16 {%0,%1,%2,%3}, [%4];"
                 : "=r"(r[0]), "=r"(r[1]), "=r"(r[2]), "=r"(r[3]) : "r"(addr));
}

// fp16 mma
__device__ __forceinline__ void mma16816h(float* d, const uint32_t* a,
                                          uint32_t b0, uint32_t b1) {
    asm volatile(
        "mma.sync.aligned.m16n8k16.row.col.f32.f16.f16.f32 "
        "{%0,%1,%2,%3}, {%4,%5,%6,%7}, {%8,%9}, {%0,%1,%2,%3};"
        : "+f"(d[0]), "+f"(d[1]), "+f"(d[2]), "+f"(d[3])
        : "r"(a[0]), "r"(a[1]), "r"(a[2]), "r"(a[3]), "r"(b0), "r"(b1));
}

// pack two fp32 -> f16x2 (lo in lower half)
__device__ __forceinline__ uint32_t packh(float lo, float hi) {
    uint32_t d;
    asm("cvt.rn.f16x2.f32 %0, %1, %2;" : "=r"(d) : "f"(hi), "f"(lo));
    return d;
}

__device__ __forceinline__ float ex2f(float x) {
    float y;
    asm("ex2.approx.f32 %0, %1;" : "=f"(y) : "f"(x));
    return y;
}

// ---------------------------------------------------------------------------
// Fused fp32 -> fp16 split: x gets (hi, lo); weights get hi only (their lo
// plane is never used by the 2-pass GEMMs).
// ---------------------------------------------------------------------------
constexpr int SPL_N0 = 1048576;            // x
constexpr int SPL_N1 = SPL_N0 + 262144;    // + w_tor
constexpr int SPL_N2 = SPL_N1 + 786432;    // + in_w
constexpr int SPL_N3 = SPL_N2 + 262144;    // + out_w  (total)

__global__ void split_all(const float* __restrict__ x, const float* __restrict__ wt,
                          const float* __restrict__ wi, const float* __restrict__ wo,
                          __half* __restrict__ xh, __half* __restrict__ xl,
                          __half* __restrict__ wth, __half* __restrict__ wih,
                          __half* __restrict__ woh)
{
    int i = blockIdx.x * blockDim.x + threadIdx.x;
    if (i >= SPL_N3) return;
    if (i < SPL_N0) {
        float4 v = ((const float4*)x)[i];
        __half h0 = __float2half_rn(v.x), h1 = __float2half_rn(v.y);
        __half h2 = __float2half_rn(v.z), h3 = __float2half_rn(v.w);
        __half l0 = __float2half_rn(v.x - __half2float(h0));
        __half l1 = __float2half_rn(v.y - __half2float(h1));
        __half l2 = __float2half_rn(v.z - __half2float(h2));
        __half l3 = __float2half_rn(v.w - __half2float(h3));
        ((__half2*)xh)[2 * i]     = __halves2half2(h0, h1);
        ((__half2*)xh)[2 * i + 1] = __halves2half2(h2, h3);
        ((__half2*)xl)[2 * i]     = __halves2half2(l0, l1);
        ((__half2*)xl)[2 * i + 1] = __halves2half2(l2, l3);
    } else {
        const float* in; __half* hi; int base;
        if (i < SPL_N1)      { in = wt; hi = wth; base = SPL_N0; }
        else if (i < SPL_N2) { in = wi; hi = wih; base = SPL_N1; }
        else                 { in = wo; hi = woh; base = SPL_N2; }
        i -= base;
        float4 v = ((const float4*)in)[i];
        ((__half2*)hi)[2 * i]     = __halves2half2(__float2half_rn(v.x), __float2half_rn(v.y));
        ((__half2*)hi)[2 * i + 1] = __halves2half2(__float2half_rn(v.z), __float2half_rn(v.w));
    }
}

// ---------------------------------------------------------------------------
// FP16 2-pass GEMM: C = (Ah + Al) @ Bh^T + bias  (B lo dropped; incoherent
// weight-rounding error ~1.2e-4 rel). CTA 128x128, 8 warps (warp 32x64),
// BK=32, double buffer, single-sync pipeline, 80B padded rows, 2 CTAs/SM.
// Stage = 3 tiles (Ah, Al, Bh) = 30KB.
// MODE 0: fp32 C.   MODE 1: fp16 split C.   MODE 2: fp16 split, lo skipped
// for columns in [E, 2E) (the K third — attention reads k_hi only).
// ---------------------------------------------------------------------------
constexpr int RB      = 80;
constexpr int TILE_B  = 128 * RB;          // 10240
constexpr int STAGE_B = 3 * TILE_B;        // 30720
constexpr int GSMEM   = 2 * STAGE_B;       // 61440 -> 2 CTAs/SM

template<int MODE>
__global__ __launch_bounds__(256, 2) void gemm_f16x2_hmma(
    const __half* __restrict__ Ahp, const __half* __restrict__ Alp,
    const __half* __restrict__ Bhp,
    const float* __restrict__ bias,
    float* __restrict__ Cf,
    __half* __restrict__ Chi, __half* __restrict__ Clo,
    int Nn, int Kk)
{
    extern __shared__ char smem[];
    const uint32_t sb = smem_u32(smem);

    const int tid  = threadIdx.x;
    const int wid  = tid >> 5;
    const int lane = tid & 31;
    const int m0 = blockIdx.y * 128;
    const int n0 = blockIdx.x * 128;

    const int lrow = tid >> 1;
    const int lhalf = (tid & 1) * 32;
    const __half* srcs[3] = {
        Ahp + (size_t)(m0 + lrow) * Kk,
        Alp + (size_t)(m0 + lrow) * Kk,
        Bhp + (size_t)(n0 + lrow) * Kk };

    auto load_stage = [&](int st, int k0) {
        uint32_t dbase = sb + st * STAGE_B + lrow * RB + lhalf;
        #pragma unroll
        for (int t = 0; t < 3; t++) {
            const __half* s = srcs[t] + k0 + (lhalf >> 1);
            cp16(dbase + t * TILE_B,      s);
            cp16(dbase + t * TILE_B + 16, s + 8);
        }
    };

    float acc[2][8][4];
    #pragma unroll
    for (int i = 0; i < 2; i++)
        #pragma unroll
        for (int j = 0; j < 8; j++)
            #pragma unroll
            for (int q = 0; q < 4; q++) acc[i][j][q] = 0.f;

    const int wm = (wid & 3) * 32;
    const int wn = (wid >> 2) * 64;
    const int lr  = lane & 15;
    const int lc  = (lane >> 4) * 16;

    const int NCH = Kk / 32;
    load_stage(0, 0);
    CP_COMMIT();

    for (int c = 0; c < NCH; c++) {
        CP_WAIT(0);
        __syncthreads();
        if (c + 1 < NCH) { load_stage((c + 1) & 1, (c + 1) * 32); CP_COMMIT(); }

        const uint32_t stb = sb + (c & 1) * STAGE_B;
        #pragma unroll
        for (int ks = 0; ks < 2; ks++) {
            const uint32_t koff = ks * 32 + lc;
            uint32_t ah[2][4], al[2][4], bb[4][4];

            uint32_t aad = stb + (wm + lr) * RB + koff;
            ldsm4(ah[0], aad);
            ldsm4(ah[1], aad + 16 * RB);

            uint32_t bad = stb + 2 * TILE_B + (wn + lr) * RB + koff;
            ldsm4(bb[0], bad);
            ldsm4(bb[1], bad + 16 * RB);
            ldsm4(bb[2], bad + 32 * RB);
            ldsm4(bb[3], bad + 48 * RB);

            // pass 1: Ah * Bh
            #pragma unroll
            for (int mi = 0; mi < 2; mi++)
                #pragma unroll
                for (int nj = 0; nj < 8; nj++)
                    mma16816h(acc[mi][nj], ah[mi], bb[nj >> 1][nj & 1], bb[nj >> 1][2 + (nj & 1)]);

            // pass 2: Al * Bh
            uint32_t aal = stb + TILE_B + (wm + lr) * RB + koff;
            ldsm4(al[0], aal);
            ldsm4(al[1], aal + 16 * RB);
            #pragma unroll
            for (int mi = 0; mi < 2; mi++)
                #pragma unroll
                for (int nj = 0; nj < 8; nj++)
                    mma16816h(acc[mi][nj], al[mi], bb[nj >> 1][nj & 1], bb[nj >> 1][2 + (nj & 1)]);
        }
    }

    const int rbase = m0 + wm + (lane >> 2);
    const int cbase = n0 + wn + (lane & 3) * 2;
    #pragma unroll
    for (int mi = 0; mi < 2; mi++) {
        #pragma unroll
        for (int nj = 0; nj < 8; nj++) {
            const int cc = cbase + nj * 8;
            float2 bv = *(const float2*)&bias[cc];
            const int r0 = rbase + mi * 16;
            float v0 = acc[mi][nj][0] + bv.x;
            float v1 = acc[mi][nj][1] + bv.y;
            float v2 = acc[mi][nj][2] + bv.x;
            float v3 = acc[mi][nj][3] + bv.y;
            if (MODE == 0) {
                *(float2*)&Cf[(size_t)r0 * Nn + cc]       = make_float2(v0, v1);
                *(float2*)&Cf[(size_t)(r0 + 8) * Nn + cc] = make_float2(v2, v3);
            } else {
                __half h0 = __float2half_rn(v0), h1 = __float2half_rn(v1);
                __half h2 = __float2half_rn(v2), h3 = __float2half_rn(v3);
                *(__half2*)(Chi + (size_t)r0 * Nn + cc)       = __halves2half2(h0, h1);
                *(__half2*)(Chi + (size_t)(r0 + 8) * Nn + cc) = __halves2half2(h2, h3);
                if (MODE == 1 || cc < E || cc >= 2 * E) {
                    __half l0 = __float2half_rn(v0 - __half2float(h0));
                    __half l1 = __float2half_rn(v1 - __half2float(h1));
                    __half l2 = __float2half_rn(v2 - __half2float(h2));
                    __half l3 = __float2half_rn(v3 - __half2float(h3));
                    *(__half2*)(Clo + (size_t)r0 * Nn + cc)       = __halves2half2(l0, l1);
                    *(__half2*)(Clo + (size_t)(r0 + 8) * Nn + cc) = __halves2half2(l2, l3);
                }
            }
        }
    }
}

// ---------------------------------------------------------------------------
// FP16 HMMA flash-attention (R15 design). Output now fp16 split (GEMM3's A).
// ---------------------------------------------------------------------------
constexpr int ARD    = 144;
constexpr int AQTILE = 128 * ARD;
constexpr int AQH = 0, AQL = AQTILE;
constexpr int ASTG0  = 2 * AQTILE;                 // 36864
constexpr int KTILE  = 64 * ARD;                   // 9216
constexpr int ASTGB  = 2 * KTILE;                  // Kh, Vh = 18432
constexpr int AKH = 0, AVH = KTILE;
constexpr int ASMEM  = ASTG0 + 2 * ASTGB;          // 73728

__global__ __launch_bounds__(256, 2) void attn_toroidal_mma(
    const __half* __restrict__ qkh, const __half* __restrict__ qkl,
    __half* __restrict__ ohi, __half* __restrict__ olo)
{
    extern __shared__ char smc[];
    const uint32_t sb = smem_u32(smc);
    const int tid = threadIdx.x, wid = tid >> 5, lane = tid & 31;
    const int bh = blockIdx.x, b = bh >> 4, h = bh & 15;
    const int q0 = blockIdx.y * 128;

    const size_t RS = 6144;
    const __half* qh_p = qkh + (size_t)b * 3 * E + h * HD;
    const __half* ql_p = qkl + (size_t)b * 3 * E + h * HD;
    const __half* kh_p = qh_p + E;
    const __half* vh_p = qh_p + 2 * E;

    auto load_q = [&]() {
        #pragma unroll
        for (int i = 0; i < 4; i++) {
            int cid = tid + i * 256;
            int row = cid >> 3, ch = cid & 7;
            uint32_t d = sb + row * ARD + ch * 16;
            cp16(d + AQH, qh_p + (size_t)(q0 + row) * RS + ch * 8);
            cp16(d + AQL, ql_p + (size_t)(q0 + row) * RS + ch * 8);
        }
    };
    auto load_kv = [&](int st, int kt) {
        const __half* bases[2] = { kh_p, vh_p };
        uint32_t stg = sb + ASTG0 + st * ASTGB;
        #pragma unroll
        for (int t = 0; t < 2; t++) {
            #pragma unroll
            for (int i = 0; i < 2; i++) {
                int cid = tid + i * 256;
                int row = cid >> 3, ch = cid & 7;
                cp16(stg + t * KTILE + row * ARD + ch * 16,
                     bases[t] + (size_t)(kt * 64 + row) * RS + ch * 8);
            }
        }
    };

    load_q();
    load_kv(0, 0);
    CP_COMMIT();

    const int lr4 = lane >> 2;
    const int lc2 = (lane & 3) * 2;
    const int rowA = q0 + wid * 16 + lr4;
    const int rowB = rowA + 8;

    float Ov[8][4];
    #pragma unroll
    for (int j = 0; j < 8; j++)
        #pragma unroll
        for (int q = 0; q < 4; q++) Ov[j][q] = 0.f;
    float lA = 0.f, lB = 0.f;

    const uint32_t lrow = lane & 15;
    const uint32_t lcb  = (lane >> 4) * 16;
    const uint32_t qaddr0 = sb + (wid * 16 + lrow) * ARD + lcb;

    CP_WAIT(0);
    __syncthreads();
    uint32_t qh_f[4][4];
    #pragma unroll
    for (int ks = 0; ks < 4; ks++) ldsm4(qh_f[ks], qaddr0 + AQH + ks * 32);
    constexpr int NT = S / 64;
    load_kv(1, 1);
    CP_COMMIT();

    const float C1 = 0.18033688f;
    const float CB = 1.44269504f;

    for (int kt = 0; kt < NT; kt++) {
        if (kt > 0) {
            CP_WAIT(0);
            __syncthreads();
            if (kt + 1 < NT) { load_kv((kt + 1) & 1, kt + 1); CP_COMMIT(); }
        }
        const uint32_t stg = sb + ASTG0 + (kt & 1) * ASTGB;

        float Sv[8][4];
        #pragma unroll
        for (int nj = 0; nj < 8; nj++)
            #pragma unroll
            for (int q = 0; q < 4; q++) Sv[nj][q] = 0.f;

        #pragma unroll
        for (int ks = 0; ks < 4; ks++) {
            uint32_t al[4], kf[4][4];
            ldsm4(al, qaddr0 + AQL + ks * 32);
            uint32_t kaddr = stg + AKH + lrow * ARD + ks * 32 + lcb;
            #pragma unroll
            for (int kb = 0; kb < 4; kb++) ldsm4(kf[kb], kaddr + kb * 16 * ARD);
            #pragma unroll
            for (int nj = 0; nj < 8; nj++) {
                uint32_t b0 = kf[nj >> 1][nj & 1], b1 = kf[nj >> 1][2 + (nj & 1)];
                mma16816h(Sv[nj], qh_f[ks], b0, b1);
                mma16816h(Sv[nj], al, b0, b1);
            }
        }

        const int wband = (kt * 64 - (q0 + wid * 16)) & (S - 1);
        if (wband <= 16 || wband >= S - 64) {
            const int baseA = kt * 64 + lc2 - rowA + 1;
            const int baseB = baseA - 8;
            #pragma unroll
            for (int nj = 0; nj < 8; nj++) {
                int u0 = (baseA + nj * 8)     & (S - 1);
                int u1 = (baseA + nj * 8 + 1) & (S - 1);
                int u2 = (baseB + nj * 8)     & (S - 1);
                int u3 = (baseB + nj * 8 + 1) & (S - 1);
                Sv[nj][0] = ex2f(Sv[nj][0] * C1 + (u0 <= 2 ? CB : 0.f));
                Sv[nj][1] = ex2f(Sv[nj][1] * C1 + (u1 <= 2 ? CB : 0.f));
                Sv[nj][2] = ex2f(Sv[nj][2] * C1 + (u2 <= 2 ? CB : 0.f));
                Sv[nj][3] = ex2f(Sv[nj][3] * C1 + (u3 <= 2 ? CB : 0.f));
                lA += Sv[nj][0] + Sv[nj][1];
                lB += Sv[nj][2] + Sv[nj][3];
            }
        } else {
            #pragma unroll
            for (int nj = 0; nj < 8; nj++) {
                Sv[nj][0] = ex2f(Sv[nj][0] * C1);
                Sv[nj][1] = ex2f(Sv[nj][1] * C1);
                Sv[nj][2] = ex2f(Sv[nj][2] * C1);
                Sv[nj][3] = ex2f(Sv[nj][3] * C1);
                lA += Sv[nj][0] + Sv[nj][1];
                lB += Sv[nj][2] + Sv[nj][3];
            }
        }

        // ---- O += P V: single fp16 pass ----
        #pragma unroll
        for (int kb = 0; kb < 4; kb++) {
            uint32_t ph[4];
            #pragma unroll
            for (int half = 0; half < 2; half++) {
                const float* c = Sv[2 * kb + half];
                ph[half * 2]     = packh(c[0], c[1]);
                ph[half * 2 + 1] = packh(c[2], c[3]);
            }
            uint32_t vaddr = stg + AVH + (kb * 16 + lrow) * ARD + lcb;
            #pragma unroll
            for (int db = 0; db < 4; db++) {
                uint32_t vh4[4];
                ldsm4t(vh4, vaddr + db * 32);
                mma16816h(Ov[2 * db],     ph, vh4[0], vh4[1]);
                mma16816h(Ov[2 * db + 1], ph, vh4[2], vh4[3]);
            }
        }
    }

    // ---- epilogue: reduce l, normalize, write fp16 split ----
    lA += __shfl_xor_sync(0xffffffffu, lA, 1);
    lA += __shfl_xor_sync(0xffffffffu, lA, 2);
    lB += __shfl_xor_sync(0xffffffffu, lB, 1);
    lB += __shfl_xor_sync(0xffffffffu, lB, 2);
    const float invA = 1.f / lA, invB = 1.f / lB;
    const size_t oA = ((size_t)rowA * Bb + b) * E + h * HD;
    const size_t oB = ((size_t)rowB * Bb + b) * E + h * HD;
    #pragma unroll
    for (int nj = 0; nj < 8; nj++) {
        const int dc = nj * 8 + lc2;
        float v0 = Ov[nj][0] * invA, v1 = Ov[nj][1] * invA;
        float v2 = Ov[nj][2] * invB, v3 = Ov[nj][3] * invB;
        __half h0 = __float2half_rn(v0), h1 = __float2half_rn(v1);
        __half h2 = __float2half_rn(v2), h3 = __float2half_rn(v3);
        *(__half2*)(ohi + oA + dc) = __halves2half2(h0, h1);
        *(__half2*)(ohi + oB + dc) = __halves2half2(h2, h3);
        __half l0 = __float2half_rn(v0 - __half2float(h0));
        __half l1 = __float2half_rn(v1 - __half2float(h1));
        __half l2 = __float2half_rn(v2 - __half2float(h2));
        __half l3 = __float2half_rn(v3 - __half2float(h3));
        *(__half2*)(olo + oA + dc) = __halves2half2(l0, l1);
        *(__half2*)(olo + oB + dc) = __halves2half2(l2, l3);
    }
}

// ---------------------------------------------------------------------------
// Host side
// ---------------------------------------------------------------------------
extern "C" void kernel_launch(void* const* d_in, const int* in_sizes, int n_in,
                              void* d_out, int out_size)
{
    (void)in_sizes; (void)n_in; (void)out_size;
    const float* x     = (const float*)d_in[0];
    const float* w_tor = (const float*)d_in[1];
    const float* b_tor = (const float*)d_in[2];
    const float* in_w  = (const float*)d_in[3];
    const float* in_b  = (const float*)d_in[4];
    const float* out_w = (const float*)d_in[5];
    const float* out_b = (const float*)d_in[6];
    float* out = (float*)d_out;

    __half *x_hi, *x_lo, *wt_hi, *wi_hi, *wo_hi;
    __half *xt_hi, *xt_lo, *qk_hi, *qk_lo, *oa_hi, *oa_lo;
    cudaGetSymbolAddress((void**)&x_hi,  g_x_hi);  cudaGetSymbolAddress((void**)&x_lo,  g_x_lo);
    cudaGetSymbolAddress((void**)&wt_hi, g_wt_hi);
    cudaGetSymbolAddress((void**)&wi_hi, g_wi_hi);
    cudaGetSymbolAddress((void**)&wo_hi, g_wo_hi);
    cudaGetSymbolAddress((void**)&xt_hi, g_xt_hi); cudaGetSymbolAddress((void**)&xt_lo, g_xt_lo);
    cudaGetSymbolAddress((void**)&qk_hi, g_qk_hi); cudaGetSymbolAddress((void**)&qk_lo, g_qk_lo);
    cudaGetSymbolAddress((void**)&oa_hi, g_oa_hi); cudaGetSymbolAddress((void**)&oa_lo, g_oa_lo);

    cudaFuncSetAttribute(gemm_f16x2_hmma<0>, cudaFuncAttributeMaxDynamicSharedMemorySize, GSMEM);
    cudaFuncSetAttribute(gemm_f16x2_hmma<1>, cudaFuncAttributeMaxDynamicSharedMemorySize, GSMEM);
    cudaFuncSetAttribute(gemm_f16x2_hmma<2>, cudaFuncAttributeMaxDynamicSharedMemorySize, GSMEM);
    cudaFuncSetAttribute(attn_toroidal_mma, cudaFuncAttributeMaxDynamicSharedMemorySize, ASMEM);

    split_all<<<(SPL_N3 + 255) / 256, 256>>>(x, w_tor, in_w, out_w,
        x_hi, x_lo, wt_hi, wi_hi, wo_hi);

    // 1. xt = x @ w_tor^T + b_tor  (fp16 split output)
    gemm_f16x2_hmma<1><<<dim3(E / 128, M / 128), 256, GSMEM>>>(
        x_hi, x_lo, wt_hi, b_tor, nullptr, xt_hi, xt_lo, E, E);
    // 2. qkv = xt @ in_proj_w^T + in_proj_b  (fp16 split output; k_lo skipped)
    gemm_f16x2_hmma<2><<<dim3(3 * E / 128, M / 128), 256, GSMEM>>>(
        xt_hi, xt_lo, wi_hi, in_b, nullptr, qk_hi, qk_lo, 3 * E, E);
    // 3. attention (fp16 HMMA, 2-pass QK / 1-pass PV, fp16 split output)
    attn_toroidal_mma<<<dim3(Bb * H, S / 128), 256, ASMEM>>>(qk_hi, qk_lo, oa_hi, oa_lo);
    // 4. out = o @ out_w^T + out_b  (fp32 output)
    gemm_f16x2_hmma<0><<<dim3(E / 128, M / 128), 256, GSMEM>>>(
        oa_hi, oa_lo, wo_hi, out_b, out, nullptr, nullptr, E, E);
}

// round 17
// speedup vs baseline: 4.2761x; 1.0678x over previous
#include <cuda_runtime.h>
#include <cuda_bf16.h>
#include <cuda_fp16.h>
#include <math.h>
#include <stdint.h>

// Problem constants
constexpr int S  = 2048;
constexpr int Bb = 2;
constexpr int E  = 1024;
constexpr int H  = 16;
constexpr int HD = 64;
constexpr int M  = S * Bb;   // 4096 rows

// ---------------------------------------------------------------------------
// Scratch (__device__ globals; allocation-free rule). All fp16 content.
// ---------------------------------------------------------------------------
__device__ __align__(256) __half g_x_hi [M * E],     g_x_lo [M * E];
__device__ __align__(256) __half g_wt_hi[E * E];
__device__ __align__(256) __half g_wi_hi[3 * E * E];
__device__ __align__(256) __half g_wo_hi[E * E];
__device__ __align__(256) __half g_xt_hi[M * E],     g_xt_lo[M * E];
__device__ __align__(256) __half g_qk_hi[(size_t)M * 3 * E];
__device__ __align__(256) __half g_qk_lo[(size_t)M * 3 * E];
__device__ __align__(256) __half g_oa_hi[M * E];

// ---------------------------------------------------------------------------
// PTX helpers (baseline PTX only)
// ---------------------------------------------------------------------------
__device__ __forceinline__ uint32_t smem_u32(const void* p) {
    uint32_t a;
    asm("{ .reg .u64 t; cvta.to.shared.u64 t, %1; cvt.u32.u64 %0, t; }"
        : "=r"(a) : "l"(p));
    return a;
}

__device__ __forceinline__ void cp16(uint32_t dst, const void* src) {
    asm volatile("cp.async.cg.shared.global [%0], [%1], 16;"
                 :: "r"(dst), "l"(src) : "memory");
}
#define CP_COMMIT() asm volatile("cp.async.commit_group;" ::: "memory")
#define CP_WAIT(n)  asm volatile("cp.async.wait_group %0;" :: "n"(n) : "memory")

__device__ __forceinline__ void ldsm4(uint32_t* r, uint32_t addr) {
    asm volatile("ldmatrix.sync.aligned.m8n8.x4.shared.b16 {%0,%1,%2,%3}, [%4];"
                 : "=r"(r[0]), "=r"(r[1]), "=r"(r[2]), "=r"(r[3]) : "r"(addr));
}
__device__ __forceinline__ void ldsm4t(uint32_t* r, uint32_t addr) {
    asm volatile("ldmatrix.sync.aligned.m8n8.x4.trans.shared.b16 {%0,%1,%2,%3}, [%4];"
                 : "=r"(r[0]), "=r"(r[1]), "=r"(r[2]), "=r"(r[3]) : "r"(addr));
}

// fp16 mma
__device__ __forceinline__ void mma16816h(float* d, const uint32_t* a,
                                          uint32_t b0, uint32_t b1) {
    asm volatile(
        "mma.sync.aligned.m16n8k16.row.col.f32.f16.f16.f32 "
        "{%0,%1,%2,%3}, {%4,%5,%6,%7}, {%8,%9}, {%0,%1,%2,%3};"
        : "+f"(d[0]), "+f"(d[1]), "+f"(d[2]), "+f"(d[3])
        : "r"(a[0]), "r"(a[1]), "r"(a[2]), "r"(a[3]), "r"(b0), "r"(b1));
}

// pack two fp32 -> f16x2 (lo in lower half)
__device__ __forceinline__ uint32_t packh(float lo, float hi) {
    uint32_t d;
    asm("cvt.rn.f16x2.f32 %0, %1, %2;" : "=r"(d) : "f"(hi), "f"(lo));
    return d;
}

__device__ __forceinline__ float ex2f(float x) {
    float y;
    asm("ex2.approx.f32 %0, %1;" : "=f"(y) : "f"(x));
    return y;
}

// ---------------------------------------------------------------------------
// Fused fp32 -> fp16 split: x gets (hi, lo); weights get hi only.
// ---------------------------------------------------------------------------
constexpr int SPL_N0 = 1048576;            // x
constexpr int SPL_N1 = SPL_N0 + 262144;    // + w_tor
constexpr int SPL_N2 = SPL_N1 + 786432;    // + in_w
constexpr int SPL_N3 = SPL_N2 + 262144;    // + out_w  (total)

__global__ void split_all(const float* __restrict__ x, const float* __restrict__ wt,
                          const float* __restrict__ wi, const float* __restrict__ wo,
                          __half* __restrict__ xh, __half* __restrict__ xl,
                          __half* __restrict__ wth, __half* __restrict__ wih,
                          __half* __restrict__ woh)
{
    int i = blockIdx.x * blockDim.x + threadIdx.x;
    if (i >= SPL_N3) return;
    if (i < SPL_N0) {
        float4 v = ((const float4*)x)[i];
        __half h0 = __float2half_rn(v.x), h1 = __float2half_rn(v.y);
        __half h2 = __float2half_rn(v.z), h3 = __float2half_rn(v.w);
        __half l0 = __float2half_rn(v.x - __half2float(h0));
        __half l1 = __float2half_rn(v.y - __half2float(h1));
        __half l2 = __float2half_rn(v.z - __half2float(h2));
        __half l3 = __float2half_rn(v.w - __half2float(h3));
        ((__half2*)xh)[2 * i]     = __halves2half2(h0, h1);
        ((__half2*)xh)[2 * i + 1] = __halves2half2(h2, h3);
        ((__half2*)xl)[2 * i]     = __halves2half2(l0, l1);
        ((__half2*)xl)[2 * i + 1] = __halves2half2(l2, l3);
    } else {
        const float* in; __half* hi; int base;
        if (i < SPL_N1)      { in = wt; hi = wth; base = SPL_N0; }
        else if (i < SPL_N2) { in = wi; hi = wih; base = SPL_N1; }
        else                 { in = wo; hi = woh; base = SPL_N2; }
        i -= base;
        float4 v = ((const float4*)in)[i];
        ((__half2*)hi)[2 * i]     = __halves2half2(__float2half_rn(v.x), __float2half_rn(v.y));
        ((__half2*)hi)[2 * i + 1] = __halves2half2(__float2half_rn(v.z), __float2half_rn(v.w));
    }
}

// ---------------------------------------------------------------------------
// FP16 2-pass GEMM: C = (Ah + Al) @ Bh^T + bias. CTA 128x128, 8 warps,
// BK=32, double buffer, single-sync, 80B padded rows, 2 CTAs/SM.
// MODE 1: fp16 split C (hi+lo everywhere).
// MODE 2: fp16 split; lo stored ONLY for the Q third (cc < E) — attention
//         reads q_lo but never k_lo (2-pass QK) or v_lo (1-pass PV).
// ---------------------------------------------------------------------------
constexpr int RB      = 80;
constexpr int TILE_B  = 128 * RB;          // 10240
constexpr int STAGE_B = 3 * TILE_B;        // 30720
constexpr int GSMEM   = 2 * STAGE_B;       // 61440

template<int MODE>
__global__ __launch_bounds__(256, 2) void gemm_f16x2_hmma(
    const __half* __restrict__ Ahp, const __half* __restrict__ Alp,
    const __half* __restrict__ Bhp,
    const float* __restrict__ bias,
    __half* __restrict__ Chi, __half* __restrict__ Clo,
    int Nn, int Kk)
{
    extern __shared__ char smem[];
    const uint32_t sb = smem_u32(smem);

    const int tid  = threadIdx.x;
    const int wid  = tid >> 5;
    const int lane = tid & 31;
    const int m0 = blockIdx.y * 128;
    const int n0 = blockIdx.x * 128;

    const int lrow = tid >> 1;
    const int lhalf = (tid & 1) * 32;
    const __half* srcs[3] = {
        Ahp + (size_t)(m0 + lrow) * Kk,
        Alp + (size_t)(m0 + lrow) * Kk,
        Bhp + (size_t)(n0 + lrow) * Kk };

    auto load_stage = [&](int st, int k0) {
        uint32_t dbase = sb + st * STAGE_B + lrow * RB + lhalf;
        #pragma unroll
        for (int t = 0; t < 3; t++) {
            const __half* s = srcs[t] + k0 + (lhalf >> 1);
            cp16(dbase + t * TILE_B,      s);
            cp16(dbase + t * TILE_B + 16, s + 8);
        }
    };

    float acc[2][8][4];
    #pragma unroll
    for (int i = 0; i < 2; i++)
        #pragma unroll
        for (int j = 0; j < 8; j++)
            #pragma unroll
            for (int q = 0; q < 4; q++) acc[i][j][q] = 0.f;

    const int wm = (wid & 3) * 32;
    const int wn = (wid >> 2) * 64;
    const int lr  = lane & 15;
    const int lc  = (lane >> 4) * 16;

    const int NCH = Kk / 32;
    load_stage(0, 0);
    CP_COMMIT();

    for (int c = 0; c < NCH; c++) {
        CP_WAIT(0);
        __syncthreads();
        if (c + 1 < NCH) { load_stage((c + 1) & 1, (c + 1) * 32); CP_COMMIT(); }

        const uint32_t stb = sb + (c & 1) * STAGE_B;
        #pragma unroll
        for (int ks = 0; ks < 2; ks++) {
            const uint32_t koff = ks * 32 + lc;
            uint32_t ah[2][4], al[2][4], bb[4][4];

            uint32_t aad = stb + (wm + lr) * RB + koff;
            ldsm4(ah[0], aad);
            ldsm4(ah[1], aad + 16 * RB);

            uint32_t bad = stb + 2 * TILE_B + (wn + lr) * RB + koff;
            ldsm4(bb[0], bad);
            ldsm4(bb[1], bad + 16 * RB);
            ldsm4(bb[2], bad + 32 * RB);
            ldsm4(bb[3], bad + 48 * RB);

            #pragma unroll
            for (int mi = 0; mi < 2; mi++)
                #pragma unroll
                for (int nj = 0; nj < 8; nj++)
                    mma16816h(acc[mi][nj], ah[mi], bb[nj >> 1][nj & 1], bb[nj >> 1][2 + (nj & 1)]);

            uint32_t aal = stb + TILE_B + (wm + lr) * RB + koff;
            ldsm4(al[0], aal);
            ldsm4(al[1], aal + 16 * RB);
            #pragma unroll
            for (int mi = 0; mi < 2; mi++)
                #pragma unroll
                for (int nj = 0; nj < 8; nj++)
                    mma16816h(acc[mi][nj], al[mi], bb[nj >> 1][nj & 1], bb[nj >> 1][2 + (nj & 1)]);
        }
    }

    const int rbase = m0 + wm + (lane >> 2);
    const int cbase = n0 + wn + (lane & 3) * 2;
    #pragma unroll
    for (int mi = 0; mi < 2; mi++) {
        #pragma unroll
        for (int nj = 0; nj < 8; nj++) {
            const int cc = cbase + nj * 8;
            float2 bv = *(const float2*)&bias[cc];
            const int r0 = rbase + mi * 16;
            float v0 = acc[mi][nj][0] + bv.x;
            float v1 = acc[mi][nj][1] + bv.y;
            float v2 = acc[mi][nj][2] + bv.x;
            float v3 = acc[mi][nj][3] + bv.y;
            __half h0 = __float2half_rn(v0), h1 = __float2half_rn(v1);
            __half h2 = __float2half_rn(v2), h3 = __float2half_rn(v3);
            *(__half2*)(Chi + (size_t)r0 * Nn + cc)       = __halves2half2(h0, h1);
            *(__half2*)(Chi + (size_t)(r0 + 8) * Nn + cc) = __halves2half2(h2, h3);
            if (MODE == 1 || cc < E) {
                __half l0 = __float2half_rn(v0 - __half2float(h0));
                __half l1 = __float2half_rn(v1 - __half2float(h1));
                __half l2 = __float2half_rn(v2 - __half2float(h2));
                __half l3 = __float2half_rn(v3 - __half2float(h3));
                *(__half2*)(Clo + (size_t)r0 * Nn + cc)       = __halves2half2(l0, l1);
                *(__half2*)(Clo + (size_t)(r0 + 8) * Nn + cc) = __halves2half2(l2, l3);
            }
        }
    }
}

// ---------------------------------------------------------------------------
// FP16 SINGLE-pass GEMM (GEMM3): Cf = Ah @ Bh^T + bias, fp32 out.
// Stage = 2 tiles (Ah, Bh) = 20KB; otherwise identical structure.
// ---------------------------------------------------------------------------
constexpr int STAGE1_B = 2 * TILE_B;       // 20480
constexpr int G1SMEM   = 2 * STAGE1_B;     // 40960

__global__ __launch_bounds__(256, 2) void gemm_f16x1_hmma(
    const __half* __restrict__ Ahp, const __half* __restrict__ Bhp,
    const float* __restrict__ bias, float* __restrict__ Cf,
    int Nn, int Kk)
{
    extern __shared__ char smem[];
    const uint32_t sb = smem_u32(smem);

    const int tid  = threadIdx.x;
    const int wid  = tid >> 5;
    const int lane = tid & 31;
    const int m0 = blockIdx.y * 128;
    const int n0 = blockIdx.x * 128;

    const int lrow = tid >> 1;
    const int lhalf = (tid & 1) * 32;
    const __half* sA = Ahp + (size_t)(m0 + lrow) * Kk + (lhalf >> 1);
    const __half* sB = Bhp + (size_t)(n0 + lrow) * Kk + (lhalf >> 1);
    const uint32_t ldst = sb + lrow * RB + lhalf;

    auto load_stage = [&](int st, int k0) {
        uint32_t d = ldst + st * STAGE1_B;
        cp16(d,               sA + k0);
        cp16(d + 16,          sA + k0 + 8);
        cp16(d + TILE_B,      sB + k0);
        cp16(d + TILE_B + 16, sB + k0 + 8);
    };

    float acc[2][8][4];
    #pragma unroll
    for (int i = 0; i < 2; i++)
        #pragma unroll
        for (int j = 0; j < 8; j++)
            #pragma unroll
            for (int q = 0; q < 4; q++) acc[i][j][q] = 0.f;

    const int wm = (wid & 3) * 32;
    const int wn = (wid >> 2) * 64;
    const int lr  = lane & 15;
    const int lc  = (lane >> 4) * 16;

    const int NCH = Kk / 32;
    load_stage(0, 0);
    CP_COMMIT();

    for (int c = 0; c < NCH; c++) {
        CP_WAIT(0);
        __syncthreads();
        if (c + 1 < NCH) { load_stage((c + 1) & 1, (c + 1) * 32); CP_COMMIT(); }

        const uint32_t stb = sb + (c & 1) * STAGE1_B;
        #pragma unroll
        for (int ks = 0; ks < 2; ks++) {
            const uint32_t koff = ks * 32 + lc;
            uint32_t ah[2][4], bb[4][4];

            uint32_t aad = stb + (wm + lr) * RB + koff;
            ldsm4(ah[0], aad);
            ldsm4(ah[1], aad + 16 * RB);

            uint32_t bad = stb + TILE_B + (wn + lr) * RB + koff;
            ldsm4(bb[0], bad);
            ldsm4(bb[1], bad + 16 * RB);
            ldsm4(bb[2], bad + 32 * RB);
            ldsm4(bb[3], bad + 48 * RB);

            #pragma unroll
            for (int mi = 0; mi < 2; mi++)
                #pragma unroll
                for (int nj = 0; nj < 8; nj++)
                    mma16816h(acc[mi][nj], ah[mi], bb[nj >> 1][nj & 1], bb[nj >> 1][2 + (nj & 1)]);
        }
    }

    const int rbase = m0 + wm + (lane >> 2);
    const int cbase = n0 + wn + (lane & 3) * 2;
    #pragma unroll
    for (int mi = 0; mi < 2; mi++) {
        #pragma unroll
        for (int nj = 0; nj < 8; nj++) {
            const int cc = cbase + nj * 8;
            float2 bv = *(const float2*)&bias[cc];
            const int r0 = rbase + mi * 16;
            *(float2*)&Cf[(size_t)r0 * Nn + cc] =
                make_float2(acc[mi][nj][0] + bv.x, acc[mi][nj][1] + bv.y);
            *(float2*)&Cf[(size_t)(r0 + 8) * Nn + cc] =
                make_float2(acc[mi][nj][2] + bv.x, acc[mi][nj][3] + bv.y);
        }
    }
}

// ---------------------------------------------------------------------------
// FP16 HMMA flash-attention (R15/R16 design). Output: o_hi only (GEMM3 is
// single-pass and never reads o_lo).
// ---------------------------------------------------------------------------
constexpr int ARD    = 144;
constexpr int AQTILE = 128 * ARD;
constexpr int AQH = 0, AQL = AQTILE;
constexpr int ASTG0  = 2 * AQTILE;                 // 36864
constexpr int KTILE  = 64 * ARD;                   // 9216
constexpr int ASTGB  = 2 * KTILE;                  // Kh, Vh = 18432
constexpr int AKH = 0, AVH = KTILE;
constexpr int ASMEM  = ASTG0 + 2 * ASTGB;          // 73728

__global__ __launch_bounds__(256, 2) void attn_toroidal_mma(
    const __half* __restrict__ qkh, const __half* __restrict__ qkl,
    __half* __restrict__ ohi)
{
    extern __shared__ char smc[];
    const uint32_t sb = smem_u32(smc);
    const int tid = threadIdx.x, wid = tid >> 5, lane = tid & 31;
    const int bh = blockIdx.x, b = bh >> 4, h = bh & 15;
    const int q0 = blockIdx.y * 128;

    const size_t RS = 6144;
    const __half* qh_p = qkh + (size_t)b * 3 * E + h * HD;
    const __half* ql_p = qkl + (size_t)b * 3 * E + h * HD;
    const __half* kh_p = qh_p + E;
    const __half* vh_p = qh_p + 2 * E;

    auto load_q = [&]() {
        #pragma unroll
        for (int i = 0; i < 4; i++) {
            int cid = tid + i * 256;
            int row = cid >> 3, ch = cid & 7;
            uint32_t d = sb + row * ARD + ch * 16;
            cp16(d + AQH, qh_p + (size_t)(q0 + row) * RS + ch * 8);
            cp16(d + AQL, ql_p + (size_t)(q0 + row) * RS + ch * 8);
        }
    };
    auto load_kv = [&](int st, int kt) {
        const __half* bases[2] = { kh_p, vh_p };
        uint32_t stg = sb + ASTG0 + st * ASTGB;
        #pragma unroll
        for (int t = 0; t < 2; t++) {
            #pragma unroll
            for (int i = 0; i < 2; i++) {
                int cid = tid + i * 256;
                int row = cid >> 3, ch = cid & 7;
                cp16(stg + t * KTILE + row * ARD + ch * 16,
                     bases[t] + (size_t)(kt * 64 + row) * RS + ch * 8);
            }
        }
    };

    load_q();
    load_kv(0, 0);
    CP_COMMIT();

    const int lr4 = lane >> 2;
    const int lc2 = (lane & 3) * 2;
    const int rowA = q0 + wid * 16 + lr4;
    const int rowB = rowA + 8;

    float Ov[8][4];
    #pragma unroll
    for (int j = 0; j < 8; j++)
        #pragma unroll
        for (int q = 0; q < 4; q++) Ov[j][q] = 0.f;
    float lA = 0.f, lB = 0.f;

    const uint32_t lrow = lane & 15;
    const uint32_t lcb  = (lane >> 4) * 16;
    const uint32_t qaddr0 = sb + (wid * 16 + lrow) * ARD + lcb;

    CP_WAIT(0);
    __syncthreads();
    uint32_t qh_f[4][4];
    #pragma unroll
    for (int ks = 0; ks < 4; ks++) ldsm4(qh_f[ks], qaddr0 + AQH + ks * 32);
    constexpr int NT = S / 64;
    load_kv(1, 1);
    CP_COMMIT();

    const float C1 = 0.18033688f;
    const float CB = 1.44269504f;

    for (int kt = 0; kt < NT; kt++) {
        if (kt > 0) {
            CP_WAIT(0);
            __syncthreads();
            if (kt + 1 < NT) { load_kv((kt + 1) & 1, kt + 1); CP_COMMIT(); }
        }
        const uint32_t stg = sb + ASTG0 + (kt & 1) * ASTGB;

        float Sv[8][4];
        #pragma unroll
        for (int nj = 0; nj < 8; nj++)
            #pragma unroll
            for (int q = 0; q < 4; q++) Sv[nj][q] = 0.f;

        #pragma unroll
        for (int ks = 0; ks < 4; ks++) {
            uint32_t al[4], kf[4][4];
            ldsm4(al, qaddr0 + AQL + ks * 32);
            uint32_t kaddr = stg + AKH + lrow * ARD + ks * 32 + lcb;
            #pragma unroll
            for (int kb = 0; kb < 4; kb++) ldsm4(kf[kb], kaddr + kb * 16 * ARD);
            #pragma unroll
            for (int nj = 0; nj < 8; nj++) {
                uint32_t b0 = kf[nj >> 1][nj & 1], b1 = kf[nj >> 1][2 + (nj & 1)];
                mma16816h(Sv[nj], qh_f[ks], b0, b1);
                mma16816h(Sv[nj], al, b0, b1);
            }
        }

        const int wband = (kt * 64 - (q0 + wid * 16)) & (S - 1);
        if (wband <= 16 || wband >= S - 64) {
            const int baseA = kt * 64 + lc2 - rowA + 1;
            const int baseB = baseA - 8;
            #pragma unroll
            for (int nj = 0; nj < 8; nj++) {
                int u0 = (baseA + nj * 8)     & (S - 1);
                int u1 = (baseA + nj * 8 + 1) & (S - 1);
                int u2 = (baseB + nj * 8)     & (S - 1);
                int u3 = (baseB + nj * 8 + 1) & (S - 1);
                Sv[nj][0] = ex2f(Sv[nj][0] * C1 + (u0 <= 2 ? CB : 0.f));
                Sv[nj][1] = ex2f(Sv[nj][1] * C1 + (u1 <= 2 ? CB : 0.f));
                Sv[nj][2] = ex2f(Sv[nj][2] * C1 + (u2 <= 2 ? CB : 0.f));
                Sv[nj][3] = ex2f(Sv[nj][3] * C1 + (u3 <= 2 ? CB : 0.f));
                lA += Sv[nj][0] + Sv[nj][1];
                lB += Sv[nj][2] + Sv[nj][3];
            }
        } else {
            #pragma unroll
            for (int nj = 0; nj < 8; nj++) {
                Sv[nj][0] = ex2f(Sv[nj][0] * C1);
                Sv[nj][1] = ex2f(Sv[nj][1] * C1);
                Sv[nj][2] = ex2f(Sv[nj][2] * C1);
                Sv[nj][3] = ex2f(Sv[nj][3] * C1);
                lA += Sv[nj][0] + Sv[nj][1];
                lB += Sv[nj][2] + Sv[nj][3];
            }
        }

        // ---- O += P V: single fp16 pass ----
        #pragma unroll
        for (int kb = 0; kb < 4; kb++) {
            uint32_t ph[4];
            #pragma unroll
            for (int half = 0; half < 2; half++) {
                const float* c = Sv[2 * kb + half];
                ph[half * 2]     = packh(c[0], c[1]);
                ph[half * 2 + 1] = packh(c[2], c[3]);
            }
            uint32_t vaddr = stg + AVH + (kb * 16 + lrow) * ARD + lcb;
            #pragma unroll
            for (int db = 0; db < 4; db++) {
                uint32_t vh4[4];
                ldsm4t(vh4, vaddr + db * 32);
                mma16816h(Ov[2 * db],     ph, vh4[0], vh4[1]);
                mma16816h(Ov[2 * db + 1], ph, vh4[2], vh4[3]);
            }
        }
    }

    // ---- epilogue: reduce l, normalize, write fp16 hi only ----
    lA += __shfl_xor_sync(0xffffffffu, lA, 1);
    lA += __shfl_xor_sync(0xffffffffu, lA, 2);
    lB += __shfl_xor_sync(0xffffffffu, lB, 1);
    lB += __shfl_xor_sync(0xffffffffu, lB, 2);
    const float invA = 1.f / lA, invB = 1.f / lB;
    const size_t oA = ((size_t)rowA * Bb + b) * E + h * HD;
    const size_t oB = ((size_t)rowB * Bb + b) * E + h * HD;
    #pragma unroll
    for (int nj = 0; nj < 8; nj++) {
        const int dc = nj * 8 + lc2;
        *(uint32_t*)(ohi + oA + dc) = packh(Ov[nj][0] * invA, Ov[nj][1] * invA);
        *(uint32_t*)(ohi + oB + dc) = packh(Ov[nj][2] * invB, Ov[nj][3] * invB);
    }
}

// ---------------------------------------------------------------------------
// Host side
// ---------------------------------------------------------------------------
extern "C" void kernel_launch(void* const* d_in, const int* in_sizes, int n_in,
                              void* d_out, int out_size)
{
    (void)in_sizes; (void)n_in; (void)out_size;
    const float* x     = (const float*)d_in[0];
    const float* w_tor = (const float*)d_in[1];
    const float* b_tor = (const float*)d_in[2];
    const float* in_w  = (const float*)d_in[3];
    const float* in_b  = (const float*)d_in[4];
    const float* out_w = (const float*)d_in[5];
    const float* out_b = (const float*)d_in[6];
    float* out = (float*)d_out;

    __half *x_hi, *x_lo, *wt_hi, *wi_hi, *wo_hi;
    __half *xt_hi, *xt_lo, *qk_hi, *qk_lo, *oa_hi;
    cudaGetSymbolAddress((void**)&x_hi,  g_x_hi);  cudaGetSymbolAddress((void**)&x_lo,  g_x_lo);
    cudaGetSymbolAddress((void**)&wt_hi, g_wt_hi);
    cudaGetSymbolAddress((void**)&wi_hi, g_wi_hi);
    cudaGetSymbolAddress((void**)&wo_hi, g_wo_hi);
    cudaGetSymbolAddress((void**)&xt_hi, g_xt_hi); cudaGetSymbolAddress((void**)&xt_lo, g_xt_lo);
    cudaGetSymbolAddress((void**)&qk_hi, g_qk_hi); cudaGetSymbolAddress((void**)&qk_lo, g_qk_lo);
    cudaGetSymbolAddress((void**)&oa_hi, g_oa_hi);

    cudaFuncSetAttribute(gemm_f16x2_hmma<1>, cudaFuncAttributeMaxDynamicSharedMemorySize, GSMEM);
    cudaFuncSetAttribute(gemm_f16x2_hmma<2>, cudaFuncAttributeMaxDynamicSharedMemorySize, GSMEM);
    cudaFuncSetAttribute(gemm_f16x1_hmma, cudaFuncAttributeMaxDynamicSharedMemorySize, G1SMEM);
    cudaFuncSetAttribute(attn_toroidal_mma, cudaFuncAttributeMaxDynamicSharedMemorySize, ASMEM);

    split_all<<<(SPL_N3 + 255) / 256, 256>>>(x, w_tor, in_w, out_w,
        x_hi, x_lo, wt_hi, wi_hi, wo_hi);

    // 1. xt = x @ w_tor^T + b_tor  (fp16 split output)
    gemm_f16x2_hmma<1><<<dim3(E / 128, M / 128), 256, GSMEM>>>(
        x_hi, x_lo, wt_hi, b_tor, xt_hi, xt_lo, E, E);
    // 2. qkv = xt @ in_proj_w^T + in_proj_b  (fp16 split; lo only for Q third)
    gemm_f16x2_hmma<2><<<dim3(3 * E / 128, M / 128), 256, GSMEM>>>(
        xt_hi, xt_lo, wi_hi, in_b, qk_hi, qk_lo, 3 * E, E);
    // 3. attention (fp16 HMMA, 2-pass QK / 1-pass PV, fp16 hi output)
    attn_toroidal_mma<<<dim3(Bb * H, S / 128), 256, ASMEM>>>(qk_hi, qk_lo, oa_hi);
    // 4. out = o_hi @ out_w^T + out_b  (single-pass, fp32 output)
    gemm_f16x1_hmma<<<dim3(E / 128, M / 128), 256, G1SMEM>>>(
        oa_hi, wo_hi, out_b, out, E, E);
}